// round 11
// baseline (speedup 1.0000x reference)
#include <cuda_runtime.h>
#include <cuda_fp16.h>
#include <math.h>

#define TPB 320
#define EPB 640   // 2 elements per thread

typedef unsigned long long u64;

__device__ float gGW3[1024];   // g2-scaled W3, padded to 8 cols (scratch, benign-race identical writes)

__device__ __forceinline__ u64 pk2(float x, float y) {
    u64 r; asm("mov.b64 %0, {%1,%2};" : "=l"(r) : "f"(x), "f"(y)); return r;
}
__device__ __forceinline__ void upk2(u64 v, float& x, float& y) {
    asm("mov.b64 {%0,%1}, %2;" : "=f"(x), "=f"(y) : "l"(v));
}
__device__ __forceinline__ u64 ffma2(u64 a, u64 b, u64 c) {
    u64 d; asm("fma.rn.f32x2 %0, %1, %2, %3;" : "=l"(d) : "l"(a), "l"(b), "l"(c)); return d;
}
__device__ __forceinline__ float gelu_f(float x) {
    return 0.5f * x * (1.0f + erff(x * 0.70710678118654752440f));
}
__device__ __forceinline__ unsigned h2_as_u32(__half2 h) {
    return *reinterpret_cast<unsigned*>(&h);
}
__device__ __forceinline__ __half2 u32_as_h2(unsigned u) {
    return *reinterpret_cast<__half2*>(&u);
}

// FK for the 7-DOF Panda chain -> 7 keypoints
__device__ __forceinline__ void fk_eval(const float th[7], float kp[21]) {
    const float FR[7][9] = {
        {1,0,0,  0,1,0,   0,0,1},
        {1,0,0,  0,0,1,   0,-1,0},
        {1,0,0,  0,0,-1,  0,1,0},
        {1,0,0,  0,0,-1,  0,1,0},
        {1,0,0,  0,0,1,   0,-1,0},
        {1,0,0,  0,0,-1,  0,1,0},
        {1,0,0,  0,0,-1,  0,1,0}
    };
    const float FT[7][3] = {
        {0.f,0.f,0.333f},{0.f,0.f,0.f},{0.f,-0.316f,0.f},{0.0825f,0.f,0.f},
        {-0.0825f,0.384f,0.f},{0.f,0.f,0.f},{0.088f,0.f,0.f}
    };
    float r[9] = {1,0,0, 0,1,0, 0,0,1};
    float t[3] = {0,0,0};
    kp[0] = 0.f; kp[1] = 0.f; kp[2] = 0.f;
    int w = 3;
    #pragma unroll
    for (int i = 0; i < 7; i++) {
        float s, c; __sincosf(th[i], &s, &c);
        float sr[9];
        sr[0] =  FR[i][0]*c + FR[i][1]*s;  sr[1] = -FR[i][0]*s + FR[i][1]*c;  sr[2] = FR[i][2];
        sr[3] =  FR[i][3]*c + FR[i][4]*s;  sr[4] = -FR[i][3]*s + FR[i][4]*c;  sr[5] = FR[i][5];
        sr[6] =  FR[i][6]*c + FR[i][7]*s;  sr[7] = -FR[i][6]*s + FR[i][7]*c;  sr[8] = FR[i][8];
        float nt0 = r[0]*FT[i][0] + r[1]*FT[i][1] + r[2]*FT[i][2] + t[0];
        float nt1 = r[3]*FT[i][0] + r[4]*FT[i][1] + r[5]*FT[i][2] + t[1];
        float nt2 = r[6]*FT[i][0] + r[7]*FT[i][1] + r[8]*FT[i][2] + t[2];
        float nr[9];
        #pragma unroll
        for (int a = 0; a < 3; a++)
            #pragma unroll
            for (int bq = 0; bq < 3; bq++)
                nr[a*3+bq] = r[a*3+0]*sr[bq] + r[a*3+1]*sr[3+bq] + r[a*3+2]*sr[6+bq];
        #pragma unroll
        for (int q = 0; q < 9; q++) r[q] = nr[q];
        t[0] = nt0; t[1] = nt1; t[2] = nt2;
        if (i == 1 || i == 2 || i == 3 || i == 5 || i == 6) {
            kp[w] = t[0]; kp[w+1] = t[1]; kp[w+2] = t[2]; w += 3;
        }
    }
    kp[18] = t[0] + r[2]*0.107f;
    kp[19] = t[1] + r[5]*0.107f;
    kp[20] = t[2] + r[8]*0.107f;
}

// ---- smem float offsets ----
#define OFF_GW2   0                    // 128*128 (g1-scaled W2)
#define OFF_A2    16384                // 128
#define OFF_CB2   (OFF_A2 + 128)      // 128
#define OFF_A3    (OFF_CB2 + 128)      // 8
#define OFF_CB3   (OFF_A3 + 8)         // 8
#define OFF_T1    (OFF_CB3 + 8)        // 128: g1 during init, b1 after
#define OFF_T2    (OFF_T1 + 128)       // 128: be1 during init only
#define OFF_H     (OFF_T2 + 128)       // uint2 staging: 64 pairs * TPB * 8B
#define SMEM_BYTES (OFF_H * 4 + 64 * TPB * 8)

__global__ void __launch_bounds__(TPB, 1)
irm_kernel(const float* __restrict__ ang, const float* __restrict__ tgt,
           const float* __restrict__ Kc,  const float* __restrict__ Re,
           const float* __restrict__ te,  const int* __restrict__ vmk,
           const float* __restrict__ W1,  const float* __restrict__ b1,
           const float* __restrict__ g1,  const float* __restrict__ be1,
           const float* __restrict__ W2,  const float* __restrict__ b2,
           const float* __restrict__ g2,  const float* __restrict__ be2,
           const float* __restrict__ W3,  const float* __restrict__ b3,
           const float* __restrict__ slog, float* __restrict__ out, int Bn)
{
    extern __shared__ float sm[];
    float* sGW2 = sm + OFF_GW2;
    float* sA2  = sm + OFF_A2;
    float* sCB2 = sm + OFF_CB2;
    float* sA3  = sm + OFF_A3;
    float* sCB3 = sm + OFF_CB3;
    float* sT1  = sm + OFF_T1;   // g1 -> later b1
    float* sT2  = sm + OFF_T2;   // be1
    uint2* sH   = (uint2*)(sm + OFF_H);   // [64 pairs][TPB]

    const int tid = threadIdx.x;

    // ---- phase 1: raw W2, g1/be1, write GW3 scratch ----
    for (int i = tid; i < 16384; i += TPB) sGW2[i] = W2[i];
    if (tid < 128) { sT1[tid] = g1[tid]; sT2[tid] = be1[tid]; }
    for (int i = tid; i < 1024; i += TPB) {
        int k = i >> 3, j = i & 7;
        gGW3[i] = (j < 7) ? g2[k] * W3[k*7 + j] : 0.f;
    }
    __syncthreads();

    // ---- phase 2: fold LN1 into layer-2 constants; LN2 constants ----
    if (tid < 128) {
        float a2 = 0.f, cb2 = 0.f;
        for (int k = 0; k < 128; k++) {
            float w = sGW2[k*128 + tid];
            a2  += sT1[k] * w;
            cb2 += sT2[k] * w;
        }
        sA2[tid]  = a2;
        sCB2[tid] = cb2 + b2[tid];
    } else if (tid < 136) {
        int c = tid - 128;
        float a3 = 0.f, cb3 = 0.f;
        if (c < 7) {
            for (int k = 0; k < 128; k++) {
                float w = W3[k*7 + c];
                a3  += g2[k]  * w;
                cb3 += be2[k] * w;
            }
            cb3 += b3[c];
        }
        sA3[c]  = a3;
        sCB3[c] = cb3;
    }
    __syncthreads();

    // ---- phase 3: scale W2 in place by g1 ----
    for (int i = tid; i < 16384; i += TPB) sGW2[i] *= sT1[i >> 7];
    __syncthreads();

    // ---- phase 4: b1 into T1 (g1 no longer needed) ----
    if (tid < 128) sT1[tid] = b1[tid];
    __syncthreads();
    float* sb1 = sT1;

    // ---- two elements per thread ----
    const int b0r = blockIdx.x * EPB + tid;
    const int b1r = b0r + TPB;
    const bool v0 = (b0r < Bn), v1 = (b1r < Bn);
    const int be0  = v0 ? b0r : (Bn - 1);
    const int be1v = v1 ? b1r : (Bn - 1);

    float th0[7], th1[7];
    #pragma unroll
    for (int j = 0; j < 7; j++) { th0[j] = ang[(size_t)be0*7 + j]; th1[j] = ang[(size_t)be1v*7 + j]; }
    const float vm0 = (vmk[be0]  != 0) ? 1.f : 0.f;
    const float vm1 = (vmk[be1v] != 0) ? 1.f : 0.f;
    float ssv[3];
    #pragma unroll
    for (int j = 0; j < 3; j++) ssv[j] = 1.f / (1.f + expf(-slog[j]));

    const float LO[7] = {-2.8973f,-1.7628f,-2.8973f,-3.0718f,-2.8973f,-0.0175f,-2.8973f};
    const float HI[7] = { 2.8973f, 1.7628f, 2.8973f,-0.0698f, 2.8973f, 3.7525f, 2.8973f};

    float kp0[21], kp1[21];
    fk_eval(th0, kp0);
    fk_eval(th1, kp1);

    float* outA = out + (size_t)28 * Bn;   // all_angles (4,B,7)
    float* outK = out + (size_t)56 * Bn;   // all_kp     (4,B,7,3)

    if (v0) {
        #pragma unroll
        for (int j = 0; j < 7; j++)  outA[(size_t)be0*7 + j]  = th0[j];
        #pragma unroll
        for (int j = 0; j < 21; j++) outK[(size_t)be0*21 + j] = kp0[j];
    }
    if (v1) {
        #pragma unroll
        for (int j = 0; j < 7; j++)  outA[(size_t)be1v*7 + j]  = th1[j];
        #pragma unroll
        for (int j = 0; j < 21; j++) outK[(size_t)be1v*21 + j] = kp1[j];
    }

    for (int it = 0; it < 3; it++) {
        // ---- features for both elements ----
        float x0[28], x1[28];
        float mx0 = 0.f, mx1 = 0.f;
        #pragma unroll 1
        for (int e = 0; e < 2; e++) {
            const int bb = e ? be1v : be0;
            const float vm = e ? vm1 : vm0;
            const float* kp = e ? kp1 : kp0;
            const float* th = e ? th1 : th0;
            float* x = e ? x1 : x0;
            float Rm[9], Km[6], tv[3];
            #pragma unroll
            for (int j = 0; j < 9; j++) Rm[j] = Re[(size_t)bb*9 + j];
            #pragma unroll
            for (int j = 0; j < 6; j++) Km[j] = Kc[(size_t)bb*9 + j];
            #pragma unroll
            for (int j = 0; j < 3; j++) tv[j] = te[(size_t)bb*3 + j];
            float mx = 0.f;
            #pragma unroll
            for (int k = 0; k < 7; k++) {
                float px = kp[3*k], py = kp[3*k+1], pz = kp[3*k+2];
                float cx = Rm[0]*px + Rm[1]*py + Rm[2]*pz + tv[0];
                float cy = Rm[3]*px + Rm[4]*py + Rm[5]*pz + tv[1];
                float cz = Rm[6]*px + Rm[7]*py + Rm[8]*pz + tv[2];
                float z  = fmaxf(cz, 1e-6f);
                float inv = 1.0f / z;
                float nx = cx*inv, ny = cy*inv, nz = cz*inv;
                float u = Km[0]*nx + Km[1]*ny + Km[2]*nz;
                float v = Km[3]*nx + Km[4]*ny + Km[5]*nz;
                float dx = (tgt[(size_t)bb*14 + 2*k]   - u) * vm;
                float dy = (tgt[(size_t)bb*14 + 2*k+1] - v) * vm;
                x[2*k] = dx; x[2*k+1] = dy;
                float dm = sqrtf(dx*dx + dy*dy);
                x[21+k] = dm;
                mx = fmaxf(mx, dm);
            }
            #pragma unroll
            for (int j = 0; j < 7; j++) { x[14+j] = th[j]; mx = fmaxf(mx, fabsf(th[j])); }
            if (e) mx1 = mx; else mx0 = mx;
        }
        const float s0 = 64.f / (1.f + mx0);
        const float s1 = 64.f / (1.f + mx1);

        // ---- layer 1: 4 passes of 32 units, E=2; W1 from gmem (broadcast) ----
        float sum1a = 0.f, sq1a = 0.f, sum1b = 0.f, sq1b = 0.f;
        #pragma unroll 1
        for (int p = 0; p < 4; p++) {
            u64 acc0[16], acc1[16];
            const u64* pb1 = (const u64*)sb1 + p*16;
            #pragma unroll
            for (int i = 0; i < 16; i++) { u64 bi = pb1[i]; acc0[i] = bi; acc1[i] = bi; }
            const float* wbase = W1 + p*32;
            #pragma unroll 4
            for (int k = 0; k < 28; k++) {
                u64 xa = pk2(x0[k], x0[k]);
                u64 xb = pk2(x1[k], x1[k]);
                const ulonglong2* wrow = (const ulonglong2*)(wbase + k*128);
                #pragma unroll
                for (int i = 0; i < 8; i++) {
                    ulonglong2 w = wrow[i];
                    acc0[2*i]   = ffma2(xa, w.x, acc0[2*i]);
                    acc0[2*i+1] = ffma2(xa, w.y, acc0[2*i+1]);
                    acc1[2*i]   = ffma2(xb, w.x, acc1[2*i]);
                    acc1[2*i+1] = ffma2(xb, w.y, acc1[2*i+1]);
                }
            }
            #pragma unroll
            for (int i = 0; i < 16; i++) {
                float a0, a1; upk2(acc0[i], a0, a1);
                __half2 h2a = __float22half2_rn(make_float2(gelu_f(a0)*s0, gelu_f(a1)*s0));
                float2 ra = __half22float2(h2a);
                sum1a += ra.x + ra.y; sq1a += ra.x*ra.x + ra.y*ra.y;
                float c0, c1; upk2(acc1[i], c0, c1);
                __half2 h2b = __float22half2_rn(make_float2(gelu_f(c0)*s1, gelu_f(c1)*s1));
                float2 rb = __half22float2(h2b);
                sum1b += rb.x + rb.y; sq1b += rb.x*rb.x + rb.y*rb.y;
                sH[(p*16 + i)*TPB + tid] = make_uint2(h2_as_u32(h2a), h2_as_u32(h2b));
            }
        }
        float mu1a = sum1a * (1.f/128.f);
        float mu1b = sum1b * (1.f/128.f);
        float rstd1a = rsqrtf(sq1a*(1.f/128.f) - mu1a*mu1a + 1e-5f*s0*s0);
        float m1a    = -mu1a * rstd1a;
        float rstd1b = rsqrtf(sq1b*(1.f/128.f) - mu1b*mu1b + 1e-5f*s1*s1);
        float m1b    = -mu1b * rstd1b;

        // ---- layer 2: 4 passes of 32 units, E=2; h double-buffered ----
        float sum2a = 0.f, sq2a = 0.f, sum2b = 0.f, sq2b = 0.f;
        float S0[7] = {0,0,0,0,0,0,0};
        float S1[7] = {0,0,0,0,0,0,0};
        #pragma unroll 1
        for (int p = 0; p < 4; p++) {
            u64 acc0[16], acc1[16];
            #pragma unroll
            for (int i = 0; i < 16; i++) { acc0[i] = pk2(0.f,0.f); acc1[i] = pk2(0.f,0.f); }
            const float* wbase = sGW2 + p*32;
            uint2 hw = sH[tid];
            #pragma unroll 2
            for (int j2 = 0; j2 < 64; j2++) {
                uint2 hw_n = sH[(((j2+1)&63))*TPB + tid];
                float2 fa = __half22float2(u32_as_h2(hw.x));
                float2 fb = __half22float2(u32_as_h2(hw.y));
                u64 a0 = pk2(fa.x, fa.x);
                u64 a1 = pk2(fa.y, fa.y);
                u64 bb0 = pk2(fb.x, fb.x);
                u64 bb1 = pk2(fb.y, fb.y);
                const ulonglong2* w0 = (const ulonglong2*)(wbase + (2*j2)*128);
                const ulonglong2* w1 = (const ulonglong2*)(wbase + (2*j2+1)*128);
                #pragma unroll
                for (int i = 0; i < 8; i++) {
                    ulonglong2 wa = w0[i];
                    acc0[2*i]   = ffma2(a0, wa.x, acc0[2*i]);
                    acc0[2*i+1] = ffma2(a0, wa.y, acc0[2*i+1]);
                    acc1[2*i]   = ffma2(bb0, wa.x, acc1[2*i]);
                    acc1[2*i+1] = ffma2(bb0, wa.y, acc1[2*i+1]);
                }
                #pragma unroll
                for (int i = 0; i < 8; i++) {
                    ulonglong2 wb = w1[i];
                    acc0[2*i]   = ffma2(a1, wb.x, acc0[2*i]);
                    acc0[2*i+1] = ffma2(a1, wb.y, acc0[2*i+1]);
                    acc1[2*i]   = ffma2(bb1, wb.x, acc1[2*i]);
                    acc1[2*i+1] = ffma2(bb1, wb.y, acc1[2*i+1]);
                }
                hw = hw_n;
            }
            // epilogue: LN1 consts, gelu, stats, fused GEMM3 partials (GW3 scratch)
            #pragma unroll
            for (int i = 0; i < 16; i++) {
                int u = p*32 + 2*i;
                float2 a2 = *(const float2*)(sA2 + u);
                float2 cb = *(const float2*)(sCB2 + u);
                const float4* g0p = (const float4*)(gGW3 + u*8);
                const float4* g1p = (const float4*)(gGW3 + (u+1)*8);
                float4 ga = g0p[0], gb = g0p[1], gc = g1p[0], gd = g1p[1];

                float t0, t1; upk2(acc0[i], t0, t1);
                float pre0 = fmaf(rstd1a, t0, fmaf(m1a, a2.x, cb.x));
                float pre1 = fmaf(rstd1a, t1, fmaf(m1a, a2.y, cb.y));
                float h0 = gelu_f(pre0), h1 = gelu_f(pre1);
                sum2a += h0 + h1; sq2a += h0*h0 + h1*h1;
                S0[0] = fmaf(h0, ga.x, fmaf(h1, gc.x, S0[0]));
                S0[1] = fmaf(h0, ga.y, fmaf(h1, gc.y, S0[1]));
                S0[2] = fmaf(h0, ga.z, fmaf(h1, gc.z, S0[2]));
                S0[3] = fmaf(h0, ga.w, fmaf(h1, gc.w, S0[3]));
                S0[4] = fmaf(h0, gb.x, fmaf(h1, gd.x, S0[4]));
                S0[5] = fmaf(h0, gb.y, fmaf(h1, gd.y, S0[5]));
                S0[6] = fmaf(h0, gb.z, fmaf(h1, gd.z, S0[6]));

                float u0, u1v; upk2(acc1[i], u0, u1v);
                float q0 = fmaf(rstd1b, u0, fmaf(m1b, a2.x, cb.x));
                float q1 = fmaf(rstd1b, u1v, fmaf(m1b, a2.y, cb.y));
                float k0 = gelu_f(q0), k1 = gelu_f(q1);
                sum2b += k0 + k1; sq2b += k0*k0 + k1*k1;
                S1[0] = fmaf(k0, ga.x, fmaf(k1, gc.x, S1[0]));
                S1[1] = fmaf(k0, ga.y, fmaf(k1, gc.y, S1[1]));
                S1[2] = fmaf(k0, ga.z, fmaf(k1, gc.z, S1[2]));
                S1[3] = fmaf(k0, ga.w, fmaf(k1, gc.w, S1[3]));
                S1[4] = fmaf(k0, gb.x, fmaf(k1, gd.x, S1[4]));
                S1[5] = fmaf(k0, gb.y, fmaf(k1, gd.y, S1[5]));
                S1[6] = fmaf(k0, gb.z, fmaf(k1, gd.z, S1[6]));
            }
        }
        float mu2a   = sum2a * (1.f/128.f);
        float rstd2a = rsqrtf(sq2a * (1.f/128.f) - mu2a*mu2a + 1e-5f);
        float m2a    = -mu2a * rstd2a;
        float mu2b   = sum2b * (1.f/128.f);
        float rstd2b = rsqrtf(sq2b * (1.f/128.f) - mu2b*mu2b + 1e-5f);
        float m2b    = -mu2b * rstd2b;

        float ss = ssv[it];
        #pragma unroll
        for (int j = 0; j < 7; j++) {
            float d0 = fmaf(rstd2a, S0[j], fmaf(m2a, sA3[j], sCB3[j]));
            float n0 = th0[j] + ss * d0;
            th0[j] = fminf(fmaxf(n0, LO[j]), HI[j]);
            float d1 = fmaf(rstd2b, S1[j], fmaf(m2b, sA3[j], sCB3[j]));
            float n1 = th1[j] + ss * d1;
            th1[j] = fminf(fmaxf(n1, LO[j]), HI[j]);
        }
        fk_eval(th0, kp0);
        fk_eval(th1, kp1);

        const size_t w = (size_t)(it + 1);
        if (v0) {
            #pragma unroll
            for (int j = 0; j < 7; j++)  outA[w*(size_t)Bn*7  + (size_t)be0*7  + j] = th0[j];
            #pragma unroll
            for (int j = 0; j < 21; j++) outK[w*(size_t)Bn*21 + (size_t)be0*21 + j] = kp0[j];
        }
        if (v1) {
            #pragma unroll
            for (int j = 0; j < 7; j++)  outA[w*(size_t)Bn*7  + (size_t)be1v*7  + j] = th1[j];
            #pragma unroll
            for (int j = 0; j < 21; j++) outK[w*(size_t)Bn*21 + (size_t)be1v*21 + j] = kp1[j];
        }
    }

    if (v0) {
        #pragma unroll
        for (int j = 0; j < 7; j++)  out[(size_t)be0*7 + j] = th0[j];
        #pragma unroll
        for (int j = 0; j < 21; j++) out[(size_t)7*Bn + (size_t)be0*21 + j] = kp0[j];
    }
    if (v1) {
        #pragma unroll
        for (int j = 0; j < 7; j++)  out[(size_t)be1v*7 + j] = th1[j];
        #pragma unroll
        for (int j = 0; j < 21; j++) out[(size_t)7*Bn + (size_t)be1v*21 + j] = kp1[j];
    }
}

extern "C" void kernel_launch(void* const* d_in, const int* in_sizes, int n_in,
                              void* d_out, int out_size)
{
    const float* ang  = (const float*)d_in[0];
    const float* tgt  = (const float*)d_in[1];
    const float* Kc   = (const float*)d_in[2];
    const float* Re   = (const float*)d_in[4];
    const float* te   = (const float*)d_in[5];
    const int*   vmk  = (const int*)d_in[6];
    const float* W1   = (const float*)d_in[7];
    const float* b1   = (const float*)d_in[8];
    const float* g1   = (const float*)d_in[9];
    const float* be1  = (const float*)d_in[10];
    const float* W2   = (const float*)d_in[11];
    const float* b2   = (const float*)d_in[12];
    const float* g2   = (const float*)d_in[13];
    const float* be2  = (const float*)d_in[14];
    const float* W3   = (const float*)d_in[15];
    const float* b3   = (const float*)d_in[16];
    const float* slog = (const float*)d_in[17];

    const int Bn = in_sizes[0] / 7;
    const size_t smem = (size_t)SMEM_BYTES;

    cudaFuncSetAttribute(irm_kernel, cudaFuncAttributeMaxDynamicSharedMemorySize, (int)smem);

    const int grid = (Bn + EPB - 1) / EPB;
    irm_kernel<<<grid, TPB, smem>>>(ang, tgt, Kc, Re, te, vmk,
                                    W1, b1, g1, be1, W2, b2, g2, be2, W3, b3,
                                    slog, (float*)d_out, Bn);
}

// round 12
// speedup vs baseline: 1.1338x; 1.1338x over previous
#include <cuda_runtime.h>
#include <cuda_fp16.h>
#include <math.h>

#define TPB 256
#define EPB 512   // 2 elements per thread

typedef unsigned long long u64;

__device__ __forceinline__ u64 pk2(float x, float y) {
    u64 r; asm("mov.b64 %0, {%1,%2};" : "=l"(r) : "f"(x), "f"(y)); return r;
}
__device__ __forceinline__ void upk2(u64 v, float& x, float& y) {
    asm("mov.b64 {%0,%1}, %2;" : "=f"(x), "=f"(y) : "l"(v));
}
__device__ __forceinline__ u64 ffma2(u64 a, u64 b, u64 c) {
    u64 d; asm("fma.rn.f32x2 %0, %1, %2, %3;" : "=l"(d) : "l"(a), "l"(b), "l"(c)); return d;
}
__device__ __forceinline__ float gelu_f(float x) {
    return 0.5f * x * (1.0f + erff(x * 0.70710678118654752440f));
}
__device__ __forceinline__ unsigned h2_as_u32(__half2 h) {
    return *reinterpret_cast<unsigned*>(&h);
}
__device__ __forceinline__ __half2 u32_as_h2(unsigned u) {
    return *reinterpret_cast<__half2*>(&u);
}

// FK for the 7-DOF Panda chain -> 7 keypoints
__device__ __forceinline__ void fk_eval(const float th[7], float kp[21]) {
    const float FR[7][9] = {
        {1,0,0,  0,1,0,   0,0,1},
        {1,0,0,  0,0,1,   0,-1,0},
        {1,0,0,  0,0,-1,  0,1,0},
        {1,0,0,  0,0,-1,  0,1,0},
        {1,0,0,  0,0,1,   0,-1,0},
        {1,0,0,  0,0,-1,  0,1,0},
        {1,0,0,  0,0,-1,  0,1,0}
    };
    const float FT[7][3] = {
        {0.f,0.f,0.333f},{0.f,0.f,0.f},{0.f,-0.316f,0.f},{0.0825f,0.f,0.f},
        {-0.0825f,0.384f,0.f},{0.f,0.f,0.f},{0.088f,0.f,0.f}
    };
    float r[9] = {1,0,0, 0,1,0, 0,0,1};
    float t[3] = {0,0,0};
    kp[0] = 0.f; kp[1] = 0.f; kp[2] = 0.f;
    int w = 3;
    #pragma unroll
    for (int i = 0; i < 7; i++) {
        float s, c; __sincosf(th[i], &s, &c);
        float sr[9];
        sr[0] =  FR[i][0]*c + FR[i][1]*s;  sr[1] = -FR[i][0]*s + FR[i][1]*c;  sr[2] = FR[i][2];
        sr[3] =  FR[i][3]*c + FR[i][4]*s;  sr[4] = -FR[i][3]*s + FR[i][4]*c;  sr[5] = FR[i][5];
        sr[6] =  FR[i][6]*c + FR[i][7]*s;  sr[7] = -FR[i][6]*s + FR[i][7]*c;  sr[8] = FR[i][8];
        float nt0 = r[0]*FT[i][0] + r[1]*FT[i][1] + r[2]*FT[i][2] + t[0];
        float nt1 = r[3]*FT[i][0] + r[4]*FT[i][1] + r[5]*FT[i][2] + t[1];
        float nt2 = r[6]*FT[i][0] + r[7]*FT[i][1] + r[8]*FT[i][2] + t[2];
        float nr[9];
        #pragma unroll
        for (int a = 0; a < 3; a++)
            #pragma unroll
            for (int bq = 0; bq < 3; bq++)
                nr[a*3+bq] = r[a*3+0]*sr[bq] + r[a*3+1]*sr[3+bq] + r[a*3+2]*sr[6+bq];
        #pragma unroll
        for (int q = 0; q < 9; q++) r[q] = nr[q];
        t[0] = nt0; t[1] = nt1; t[2] = nt2;
        if (i == 1 || i == 2 || i == 3 || i == 5 || i == 6) {
            kp[w] = t[0]; kp[w+1] = t[1]; kp[w+2] = t[2]; w += 3;
        }
    }
    kp[18] = t[0] + r[2]*0.107f;
    kp[19] = t[1] + r[5]*0.107f;
    kp[20] = t[2] + r[8]*0.107f;
}

// ---- smem float offsets ----
#define OFF_W1    0                    // 28*128 raw
#define OFF_GW2   3584                 // 128*128 (g1-scaled W2)
#define OFF_GW3   (OFF_GW2 + 16384)    // 128*8 (g2-scaled W3, padded)
#define OFF_B1    (OFF_GW3 + 1024)     // 128
#define OFF_G1    (OFF_B1 + 128)
#define OFF_BE1   (OFF_G1 + 128)
#define OFF_A2    (OFF_BE1 + 128)      // 128
#define OFF_CB2   (OFF_A2 + 128)       // 128
#define OFF_A3    (OFF_CB2 + 128)      // 8
#define OFF_CB3   (OFF_A3 + 8)         // 8
#define OFF_H     (OFF_CB3 + 8)        // uint2 staging: 64 pairs * TPB * 8B
#define SMEM_BYTES (OFF_H * 4 + 64 * TPB * 8)

__global__ void __launch_bounds__(TPB, 1)
irm_kernel(const float* __restrict__ ang, const float* __restrict__ tgt,
           const float* __restrict__ Kc,  const float* __restrict__ Re,
           const float* __restrict__ te,  const int* __restrict__ vmk,
           const float* __restrict__ W1,  const float* __restrict__ b1,
           const float* __restrict__ g1,  const float* __restrict__ be1,
           const float* __restrict__ W2,  const float* __restrict__ b2,
           const float* __restrict__ g2,  const float* __restrict__ be2,
           const float* __restrict__ W3,  const float* __restrict__ b3,
           const float* __restrict__ slog, float* __restrict__ out, int Bn)
{
    extern __shared__ float sm[];
    float* sW1  = sm + OFF_W1;
    float* sGW2 = sm + OFF_GW2;
    float* sGW3 = sm + OFF_GW3;
    float* sb1  = sm + OFF_B1;
    float* sg1  = sm + OFF_G1;
    float* sbe1 = sm + OFF_BE1;
    float* sA2  = sm + OFF_A2;
    float* sCB2 = sm + OFF_CB2;
    float* sA3  = sm + OFF_A3;
    float* sCB3 = sm + OFF_CB3;
    uint2* sH   = (uint2*)(sm + OFF_H);   // [64 pairs][TPB], both elems packed

    const int tid = threadIdx.x;
    // warp phase skew: warps 4-7 rotate pass order by 2 to decorrelate
    // stall patterns between the two warps resident on each SMSP.
    const int wskew = ((tid >> 7) & 1) * 2;

    // ---- phase 1: raw weight loads + GW3 (g2-scaled W3) ----
    for (int i = tid; i < 3584;  i += TPB) sW1[i] = W1[i];
    for (int i = tid; i < 16384; i += TPB) sGW2[i] = W2[i];   // raw for now
    for (int i = tid; i < 1024;  i += TPB) {
        int k = i >> 3, j = i & 7;
        sGW3[i] = (j < 7) ? g2[k] * W3[k*7 + j] : 0.f;
    }
    if (tid < 128) {
        sb1[tid] = b1[tid]; sg1[tid] = g1[tid]; sbe1[tid] = be1[tid];
    }
    __syncthreads();

    // ---- phase 2: fold LN1 into layer-2 constants ----
    if (tid < 128) {
        float a2 = 0.f, cb2 = 0.f;
        for (int k = 0; k < 128; k++) {
            float w = sGW2[k*128 + tid];
            a2  += sg1[k]  * w;
            cb2 += sbe1[k] * w;
        }
        sA2[tid]  = a2;
        sCB2[tid] = cb2 + b2[tid];
    } else if (tid < 136) {
        int c = tid - 128;
        float a3 = 0.f, cb3 = 0.f;
        if (c < 7) {
            for (int k = 0; k < 128; k++) {
                a3  += sGW3[k*8 + c];
                cb3 += be2[k] * W3[k*7 + c];
            }
            cb3 += b3[c];
        }
        sA3[c]  = a3;
        sCB3[c] = cb3;
    }
    __syncthreads();

    // ---- phase 3: scale W2 in place by g1 ----
    for (int i = tid; i < 16384; i += TPB) sGW2[i] *= sg1[i >> 7];
    __syncthreads();

    // ---- two elements per thread ----
    const int b0r = blockIdx.x * EPB + tid;
    const int b1r = b0r + TPB;
    const bool v0 = (b0r < Bn), v1 = (b1r < Bn);
    const int be0  = v0 ? b0r : (Bn - 1);
    const int be1v = v1 ? b1r : (Bn - 1);

    float th0[7], th1[7];
    #pragma unroll
    for (int j = 0; j < 7; j++) { th0[j] = ang[(size_t)be0*7 + j]; th1[j] = ang[(size_t)be1v*7 + j]; }
    const float vm0 = (vmk[be0]  != 0) ? 1.f : 0.f;
    const float vm1 = (vmk[be1v] != 0) ? 1.f : 0.f;
    float ssv[3];
    #pragma unroll
    for (int j = 0; j < 3; j++) ssv[j] = 1.f / (1.f + expf(-slog[j]));

    const float LO[7] = {-2.8973f,-1.7628f,-2.8973f,-3.0718f,-2.8973f,-0.0175f,-2.8973f};
    const float HI[7] = { 2.8973f, 1.7628f, 2.8973f,-0.0698f, 2.8973f, 3.7525f, 2.8973f};

    float kp0[21], kp1[21];
    fk_eval(th0, kp0);
    fk_eval(th1, kp1);

    float* outA = out + (size_t)28 * Bn;   // all_angles (4,B,7)
    float* outK = out + (size_t)56 * Bn;   // all_kp     (4,B,7,3)

    if (v0) {
        #pragma unroll
        for (int j = 0; j < 7; j++)  outA[(size_t)be0*7 + j]  = th0[j];
        #pragma unroll
        for (int j = 0; j < 21; j++) outK[(size_t)be0*21 + j] = kp0[j];
    }
    if (v1) {
        #pragma unroll
        for (int j = 0; j < 7; j++)  outA[(size_t)be1v*7 + j]  = th1[j];
        #pragma unroll
        for (int j = 0; j < 21; j++) outK[(size_t)be1v*21 + j] = kp1[j];
    }

    for (int it = 0; it < 3; it++) {
        // ---- features for both elements (camera data from gmem, transient) ----
        float x0[28], x1[28];
        float mx0 = 0.f, mx1 = 0.f;
        #pragma unroll 1
        for (int e = 0; e < 2; e++) {
            const int bb = e ? be1v : be0;
            const float vm = e ? vm1 : vm0;
            const float* kp = e ? kp1 : kp0;
            const float* th = e ? th1 : th0;
            float* x = e ? x1 : x0;
            float Rm[9], Km[6], tv[3];
            #pragma unroll
            for (int j = 0; j < 9; j++) Rm[j] = Re[(size_t)bb*9 + j];
            #pragma unroll
            for (int j = 0; j < 6; j++) Km[j] = Kc[(size_t)bb*9 + j];
            #pragma unroll
            for (int j = 0; j < 3; j++) tv[j] = te[(size_t)bb*3 + j];
            float mx = 0.f;
            #pragma unroll
            for (int k = 0; k < 7; k++) {
                float px = kp[3*k], py = kp[3*k+1], pz = kp[3*k+2];
                float cx = Rm[0]*px + Rm[1]*py + Rm[2]*pz + tv[0];
                float cy = Rm[3]*px + Rm[4]*py + Rm[5]*pz + tv[1];
                float cz = Rm[6]*px + Rm[7]*py + Rm[8]*pz + tv[2];
                float z  = fmaxf(cz, 1e-6f);
                float inv = 1.0f / z;
                float nx = cx*inv, ny = cy*inv, nz = cz*inv;
                float u = Km[0]*nx + Km[1]*ny + Km[2]*nz;
                float v = Km[3]*nx + Km[4]*ny + Km[5]*nz;
                float dx = (tgt[(size_t)bb*14 + 2*k]   - u) * vm;
                float dy = (tgt[(size_t)bb*14 + 2*k+1] - v) * vm;
                x[2*k] = dx; x[2*k+1] = dy;
                float dm = sqrtf(dx*dx + dy*dy);
                x[21+k] = dm;
                mx = fmaxf(mx, dm);
            }
            #pragma unroll
            for (int j = 0; j < 7; j++) { x[14+j] = th[j]; mx = fmaxf(mx, fabsf(th[j])); }
            if (e) mx1 = mx; else mx0 = mx;
        }
        // per-element stage scales (LN is scale-invariant; keeps fp16 in range)
        const float s0 = 64.f / (1.f + mx0);
        const float s1 = 64.f / (1.f + mx1);

        // ---- layer 1: 4 passes of 32 units (skewed order), E=2; stage fp16 ----
        float sum1a = 0.f, sq1a = 0.f, sum1b = 0.f, sq1b = 0.f;
        #pragma unroll 1
        for (int pp = 0; pp < 4; pp++) {
            const int p = (pp + wskew) & 3;
            u64 acc0[16], acc1[16];
            const u64* pb1 = (const u64*)sb1 + p*16;
            #pragma unroll
            for (int i = 0; i < 16; i++) { u64 bi = pb1[i]; acc0[i] = bi; acc1[i] = bi; }
            const float* wbase = sW1 + p*32;
            #pragma unroll 4
            for (int k = 0; k < 28; k++) {
                u64 xa = pk2(x0[k], x0[k]);
                u64 xb = pk2(x1[k], x1[k]);
                const ulonglong2* wrow = (const ulonglong2*)(wbase + k*128);
                #pragma unroll
                for (int i = 0; i < 8; i++) {
                    ulonglong2 w = wrow[i];
                    acc0[2*i]   = ffma2(xa, w.x, acc0[2*i]);
                    acc0[2*i+1] = ffma2(xa, w.y, acc0[2*i+1]);
                    acc1[2*i]   = ffma2(xb, w.x, acc1[2*i]);
                    acc1[2*i+1] = ffma2(xb, w.y, acc1[2*i+1]);
                }
            }
            #pragma unroll
            for (int i = 0; i < 16; i++) {
                float a0, a1; upk2(acc0[i], a0, a1);
                __half2 h2a = __float22half2_rn(make_float2(gelu_f(a0)*s0, gelu_f(a1)*s0));
                float2 ra = __half22float2(h2a);            // rounded values for stats
                sum1a += ra.x + ra.y; sq1a += ra.x*ra.x + ra.y*ra.y;
                float c0, c1; upk2(acc1[i], c0, c1);
                __half2 h2b = __float22half2_rn(make_float2(gelu_f(c0)*s1, gelu_f(c1)*s1));
                float2 rb = __half22float2(h2b);
                sum1b += rb.x + rb.y; sq1b += rb.x*rb.x + rb.y*rb.y;
                sH[(p*16 + i)*TPB + tid] = make_uint2(h2_as_u32(h2a), h2_as_u32(h2b));
            }
        }
        float mu1a = sum1a * (1.f/128.f);
        float mu1b = sum1b * (1.f/128.f);
        // eps correction for scaled staging: rstd_eff = 1/sqrt(var_s + eps*s^2)
        float rstd1a = rsqrtf(sq1a*(1.f/128.f) - mu1a*mu1a + 1e-5f*s0*s0);
        float m1a    = -mu1a * rstd1a;
        float rstd1b = rsqrtf(sq1b*(1.f/128.f) - mu1b*mu1b + 1e-5f*s1*s1);
        float m1b    = -mu1b * rstd1b;

        // ---- layer 2: 4 passes of 32 units (skewed order), E=2; LN1 folded ----
        float sum2a = 0.f, sq2a = 0.f, sum2b = 0.f, sq2b = 0.f;
        float S0[7] = {0,0,0,0,0,0,0};
        float S1[7] = {0,0,0,0,0,0,0};
        #pragma unroll 1
        for (int pp = 0; pp < 4; pp++) {
            const int p = (pp + wskew) & 3;
            u64 acc0[16], acc1[16];
            #pragma unroll
            for (int i = 0; i < 16; i++) { acc0[i] = pk2(0.f,0.f); acc1[i] = pk2(0.f,0.f); }
            const float* wbase = sGW2 + p*32;
            #pragma unroll 2
            for (int j2 = 0; j2 < 64; j2++) {
                uint2 hw = sH[j2*TPB + tid];
                float2 fa = __half22float2(u32_as_h2(hw.x));
                float2 fb = __half22float2(u32_as_h2(hw.y));
                u64 a0 = pk2(fa.x, fa.x);
                u64 a1 = pk2(fa.y, fa.y);
                u64 bb0 = pk2(fb.x, fb.x);
                u64 bb1 = pk2(fb.y, fb.y);
                const ulonglong2* w0 = (const ulonglong2*)(wbase + (2*j2)*128);
                const ulonglong2* w1 = (const ulonglong2*)(wbase + (2*j2+1)*128);
                #pragma unroll
                for (int i = 0; i < 8; i++) {
                    ulonglong2 wa = w0[i];
                    acc0[2*i]   = ffma2(a0, wa.x, acc0[2*i]);
                    acc0[2*i+1] = ffma2(a0, wa.y, acc0[2*i+1]);
                    acc1[2*i]   = ffma2(bb0, wa.x, acc1[2*i]);
                    acc1[2*i+1] = ffma2(bb0, wa.y, acc1[2*i+1]);
                }
                #pragma unroll
                for (int i = 0; i < 8; i++) {
                    ulonglong2 wb = w1[i];
                    acc0[2*i]   = ffma2(a1, wb.x, acc0[2*i]);
                    acc0[2*i+1] = ffma2(a1, wb.y, acc0[2*i+1]);
                    acc1[2*i]   = ffma2(bb1, wb.x, acc1[2*i]);
                    acc1[2*i+1] = ffma2(bb1, wb.y, acc1[2*i+1]);
                }
            }
            // epilogue: LN1 consts, gelu, stats, fused GEMM3 partials
            #pragma unroll
            for (int i = 0; i < 16; i++) {
                int u = p*32 + 2*i;
                float2 a2 = *(const float2*)(sA2 + u);
                float2 cb = *(const float2*)(sCB2 + u);
                const float4* g0p = (const float4*)(sGW3 + u*8);
                const float4* g1p = (const float4*)(sGW3 + (u+1)*8);
                float4 ga = g0p[0], gb = g0p[1], gc = g1p[0], gd = g1p[1];

                float t0, t1; upk2(acc0[i], t0, t1);
                float pre0 = fmaf(rstd1a, t0, fmaf(m1a, a2.x, cb.x));
                float pre1 = fmaf(rstd1a, t1, fmaf(m1a, a2.y, cb.y));
                float h0 = gelu_f(pre0), h1 = gelu_f(pre1);
                sum2a += h0 + h1; sq2a += h0*h0 + h1*h1;
                S0[0] = fmaf(h0, ga.x, fmaf(h1, gc.x, S0[0]));
                S0[1] = fmaf(h0, ga.y, fmaf(h1, gc.y, S0[1]));
                S0[2] = fmaf(h0, ga.z, fmaf(h1, gc.z, S0[2]));
                S0[3] = fmaf(h0, ga.w, fmaf(h1, gc.w, S0[3]));
                S0[4] = fmaf(h0, gb.x, fmaf(h1, gd.x, S0[4]));
                S0[5] = fmaf(h0, gb.y, fmaf(h1, gd.y, S0[5]));
                S0[6] = fmaf(h0, gb.z, fmaf(h1, gd.z, S0[6]));

                float u0, u1v; upk2(acc1[i], u0, u1v);
                float q0 = fmaf(rstd1b, u0, fmaf(m1b, a2.x, cb.x));
                float q1 = fmaf(rstd1b, u1v, fmaf(m1b, a2.y, cb.y));
                float k0 = gelu_f(q0), k1 = gelu_f(q1);
                sum2b += k0 + k1; sq2b += k0*k0 + k1*k1;
                S1[0] = fmaf(k0, ga.x, fmaf(k1, gc.x, S1[0]));
                S1[1] = fmaf(k0, ga.y, fmaf(k1, gc.y, S1[1]));
                S1[2] = fmaf(k0, ga.z, fmaf(k1, gc.z, S1[2]));
                S1[3] = fmaf(k0, ga.w, fmaf(k1, gc.w, S1[3]));
                S1[4] = fmaf(k0, gb.x, fmaf(k1, gd.x, S1[4]));
                S1[5] = fmaf(k0, gb.y, fmaf(k1, gd.y, S1[5]));
                S1[6] = fmaf(k0, gb.z, fmaf(k1, gd.z, S1[6]));
            }
        }
        float mu2a   = sum2a * (1.f/128.f);
        float rstd2a = rsqrtf(sq2a * (1.f/128.f) - mu2a*mu2a + 1e-5f);
        float m2a    = -mu2a * rstd2a;
        float mu2b   = sum2b * (1.f/128.f);
        float rstd2b = rsqrtf(sq2b * (1.f/128.f) - mu2b*mu2b + 1e-5f);
        float m2b    = -mu2b * rstd2b;

        float ss = ssv[it];
        #pragma unroll
        for (int j = 0; j < 7; j++) {
            float d0 = fmaf(rstd2a, S0[j], fmaf(m2a, sA3[j], sCB3[j]));
            float n0 = th0[j] + ss * d0;
            th0[j] = fminf(fmaxf(n0, LO[j]), HI[j]);
            float d1 = fmaf(rstd2b, S1[j], fmaf(m2b, sA3[j], sCB3[j]));
            float n1 = th1[j] + ss * d1;
            th1[j] = fminf(fmaxf(n1, LO[j]), HI[j]);
        }
        fk_eval(th0, kp0);
        fk_eval(th1, kp1);

        const size_t w = (size_t)(it + 1);
        if (v0) {
            #pragma unroll
            for (int j = 0; j < 7; j++)  outA[w*(size_t)Bn*7  + (size_t)be0*7  + j] = th0[j];
            #pragma unroll
            for (int j = 0; j < 21; j++) outK[w*(size_t)Bn*21 + (size_t)be0*21 + j] = kp0[j];
        }
        if (v1) {
            #pragma unroll
            for (int j = 0; j < 7; j++)  outA[w*(size_t)Bn*7  + (size_t)be1v*7  + j] = th1[j];
            #pragma unroll
            for (int j = 0; j < 21; j++) outK[w*(size_t)Bn*21 + (size_t)be1v*21 + j] = kp1[j];
        }
    }

    if (v0) {
        #pragma unroll
        for (int j = 0; j < 7; j++)  out[(size_t)be0*7 + j] = th0[j];
        #pragma unroll
        for (int j = 0; j < 21; j++) out[(size_t)7*Bn + (size_t)be0*21 + j] = kp0[j];
    }
    if (v1) {
        #pragma unroll
        for (int j = 0; j < 7; j++)  out[(size_t)be1v*7 + j] = th1[j];
        #pragma unroll
        for (int j = 0; j < 21; j++) out[(size_t)7*Bn + (size_t)be1v*21 + j] = kp1[j];
    }
}

extern "C" void kernel_launch(void* const* d_in, const int* in_sizes, int n_in,
                              void* d_out, int out_size)
{
    const float* ang  = (const float*)d_in[0];
    const float* tgt  = (const float*)d_in[1];
    const float* Kc   = (const float*)d_in[2];
    const float* Re   = (const float*)d_in[4];
    const float* te   = (const float*)d_in[5];
    const int*   vmk  = (const int*)d_in[6];
    const float* W1   = (const float*)d_in[7];
    const float* b1   = (const float*)d_in[8];
    const float* g1   = (const float*)d_in[9];
    const float* be1  = (const float*)d_in[10];
    const float* W2   = (const float*)d_in[11];
    const float* b2   = (const float*)d_in[12];
    const float* g2   = (const float*)d_in[13];
    const float* be2  = (const float*)d_in[14];
    const float* W3   = (const float*)d_in[15];
    const float* b3   = (const float*)d_in[16];
    const float* slog = (const float*)d_in[17];

    const int Bn = in_sizes[0] / 7;
    const size_t smem = (size_t)SMEM_BYTES;

    cudaFuncSetAttribute(irm_kernel, cudaFuncAttributeMaxDynamicSharedMemorySize, (int)smem);

    const int grid = (Bn + EPB - 1) / EPB;
    irm_kernel<<<grid, TPB, smem>>>(ang, tgt, Kc, Re, te, vmk,
                                    W1, b1, g1, be1, W2, b2, g2, be2, W3, b3,
                                    slog, (float*)d_out, Bn);
}

// round 14
// speedup vs baseline: 1.1466x; 1.0113x over previous
#include <cuda_runtime.h>
#include <cuda_fp16.h>
#include <math.h>

#define TPB 256
#define EPB 512   // 2 elements per thread

typedef unsigned long long u64;

__device__ __forceinline__ u64 pk2(float x, float y) {
    u64 r; asm("mov.b64 %0, {%1,%2};" : "=l"(r) : "f"(x), "f"(y)); return r;
}
__device__ __forceinline__ void upk2(u64 v, float& x, float& y) {
    asm("mov.b64 {%0,%1}, %2;" : "=f"(x), "=f"(y) : "l"(v));
}
__device__ __forceinline__ u64 ffma2(u64 a, u64 b, u64 c) {
    u64 d; asm("fma.rn.f32x2 %0, %1, %2, %3;" : "=l"(d) : "l"(a), "l"(b), "l"(c)); return d;
}
__device__ __forceinline__ float gelu_f(float x) {
    return 0.5f * x * (1.0f + erff(x * 0.70710678118654752440f));
}
__device__ __forceinline__ unsigned h2_as_u32(__half2 h) {
    return *reinterpret_cast<unsigned*>(&h);
}
__device__ __forceinline__ __half2 u32_as_h2(unsigned u) {
    return *reinterpret_cast<__half2*>(&u);
}

// FK for the 7-DOF Panda chain -> 7 keypoints
__device__ __forceinline__ void fk_eval(const float th[7], float kp[21]) {
    const float FR[7][9] = {
        {1,0,0,  0,1,0,   0,0,1},
        {1,0,0,  0,0,1,   0,-1,0},
        {1,0,0,  0,0,-1,  0,1,0},
        {1,0,0,  0,0,-1,  0,1,0},
        {1,0,0,  0,0,1,   0,-1,0},
        {1,0,0,  0,0,-1,  0,1,0},
        {1,0,0,  0,0,-1,  0,1,0}
    };
    const float FT[7][3] = {
        {0.f,0.f,0.333f},{0.f,0.f,0.f},{0.f,-0.316f,0.f},{0.0825f,0.f,0.f},
        {-0.0825f,0.384f,0.f},{0.f,0.f,0.f},{0.088f,0.f,0.f}
    };
    float r[9] = {1,0,0, 0,1,0, 0,0,1};
    float t[3] = {0,0,0};
    kp[0] = 0.f; kp[1] = 0.f; kp[2] = 0.f;
    int w = 3;
    #pragma unroll
    for (int i = 0; i < 7; i++) {
        float s, c; __sincosf(th[i], &s, &c);
        float sr[9];
        sr[0] =  FR[i][0]*c + FR[i][1]*s;  sr[1] = -FR[i][0]*s + FR[i][1]*c;  sr[2] = FR[i][2];
        sr[3] =  FR[i][3]*c + FR[i][4]*s;  sr[4] = -FR[i][3]*s + FR[i][4]*c;  sr[5] = FR[i][5];
        sr[6] =  FR[i][6]*c + FR[i][7]*s;  sr[7] = -FR[i][6]*s + FR[i][7]*c;  sr[8] = FR[i][8];
        float nt0 = r[0]*FT[i][0] + r[1]*FT[i][1] + r[2]*FT[i][2] + t[0];
        float nt1 = r[3]*FT[i][0] + r[4]*FT[i][1] + r[5]*FT[i][2] + t[1];
        float nt2 = r[6]*FT[i][0] + r[7]*FT[i][1] + r[8]*FT[i][2] + t[2];
        float nr[9];
        #pragma unroll
        for (int a = 0; a < 3; a++)
            #pragma unroll
            for (int bq = 0; bq < 3; bq++)
                nr[a*3+bq] = r[a*3+0]*sr[bq] + r[a*3+1]*sr[3+bq] + r[a*3+2]*sr[6+bq];
        #pragma unroll
        for (int q = 0; q < 9; q++) r[q] = nr[q];
        t[0] = nt0; t[1] = nt1; t[2] = nt2;
        if (i == 1 || i == 2 || i == 3 || i == 5 || i == 6) {
            kp[w] = t[0]; kp[w+1] = t[1]; kp[w+2] = t[2]; w += 3;
        }
    }
    kp[18] = t[0] + r[2]*0.107f;
    kp[19] = t[1] + r[5]*0.107f;
    kp[20] = t[2] + r[8]*0.107f;
}

// ---- smem float offsets ----
#define OFF_W1    0                    // 28*128 raw
#define OFF_GW2   3584                 // 128*128 (g1-scaled W2)
#define OFF_GW3   (OFF_GW2 + 16384)    // 128*8 (g2-scaled W3, padded)
#define OFF_B1    (OFF_GW3 + 1024)     // 128
#define OFF_G1    (OFF_B1 + 128)
#define OFF_BE1   (OFF_G1 + 128)
#define OFF_A2    (OFF_BE1 + 128)      // 128
#define OFF_CB2   (OFF_A2 + 128)       // 128
#define OFF_A3    (OFF_CB2 + 128)      // 8
#define OFF_CB3   (OFF_A3 + 8)         // 8
#define OFF_H     (OFF_CB3 + 8)        // uint2 staging: 64 pairs * TPB * 8B
#define SMEM_BYTES (OFF_H * 4 + 64 * TPB * 8)

__global__ void __launch_bounds__(TPB, 1)
irm_kernel(const float* __restrict__ ang, const float* __restrict__ tgt,
           const float* __restrict__ Kc,  const float* __restrict__ Re,
           const float* __restrict__ te,  const int* __restrict__ vmk,
           const float* __restrict__ W1,  const float* __restrict__ b1,
           const float* __restrict__ g1,  const float* __restrict__ be1,
           const float* __restrict__ W2,  const float* __restrict__ b2,
           const float* __restrict__ g2,  const float* __restrict__ be2,
           const float* __restrict__ W3,  const float* __restrict__ b3,
           const float* __restrict__ slog, float* __restrict__ out, int Bn)
{
    extern __shared__ float sm[];
    float* sW1  = sm + OFF_W1;
    float* sGW2 = sm + OFF_GW2;
    float* sGW3 = sm + OFF_GW3;
    float* sb1  = sm + OFF_B1;
    float* sg1  = sm + OFF_G1;
    float* sbe1 = sm + OFF_BE1;
    float* sA2  = sm + OFF_A2;
    float* sCB2 = sm + OFF_CB2;
    float* sA3  = sm + OFF_A3;
    float* sCB3 = sm + OFF_CB3;
    uint2* sH   = (uint2*)(sm + OFF_H);   // [64 pairs][TPB], both elems packed

    const int tid = threadIdx.x;
    // warp phase skew: warps 4-7 rotate pass order by 2
    const int wskew = ((tid >> 7) & 1) * 2;

    // ---- phase 1: raw weight loads + GW3 (g2-scaled W3) ----
    for (int i = tid; i < 3584;  i += TPB) sW1[i] = W1[i];
    for (int i = tid; i < 16384; i += TPB) sGW2[i] = W2[i];   // raw for now
    for (int i = tid; i < 1024;  i += TPB) {
        int k = i >> 3, j = i & 7;
        sGW3[i] = (j < 7) ? g2[k] * W3[k*7 + j] : 0.f;
    }
    if (tid < 128) {
        sb1[tid] = b1[tid]; sg1[tid] = g1[tid]; sbe1[tid] = be1[tid];
    }
    __syncthreads();

    // ---- phase 2: fold LN1 into layer-2 constants ----
    if (tid < 128) {
        float a2 = 0.f, cb2 = 0.f;
        for (int k = 0; k < 128; k++) {
            float w = sGW2[k*128 + tid];
            a2  += sg1[k]  * w;
            cb2 += sbe1[k] * w;
        }
        sA2[tid]  = a2;
        sCB2[tid] = cb2 + b2[tid];
    } else if (tid < 136) {
        int c = tid - 128;
        float a3 = 0.f, cb3 = 0.f;
        if (c < 7) {
            for (int k = 0; k < 128; k++) {
                a3  += sGW3[k*8 + c];
                cb3 += be2[k] * W3[k*7 + c];
            }
            cb3 += b3[c];
        }
        sA3[c]  = a3;
        sCB3[c] = cb3;
    }
    __syncthreads();

    // ---- phase 3: scale W2 in place by g1 ----
    for (int i = tid; i < 16384; i += TPB) sGW2[i] *= sg1[i >> 7];
    __syncthreads();

    // ---- two elements per thread ----
    const int b0r = blockIdx.x * EPB + tid;
    const int b1r = b0r + TPB;
    const bool v0 = (b0r < Bn), v1 = (b1r < Bn);
    const int be0  = v0 ? b0r : (Bn - 1);
    const int be1v = v1 ? b1r : (Bn - 1);

    float th0[7], th1[7];
    #pragma unroll
    for (int j = 0; j < 7; j++) { th0[j] = ang[(size_t)be0*7 + j]; th1[j] = ang[(size_t)be1v*7 + j]; }
    const float vm0 = (vmk[be0]  != 0) ? 1.f : 0.f;
    const float vm1 = (vmk[be1v] != 0) ? 1.f : 0.f;
    float ssv[3];
    #pragma unroll
    for (int j = 0; j < 3; j++) ssv[j] = 1.f / (1.f + expf(-slog[j]));

    const float LO[7] = {-2.8973f,-1.7628f,-2.8973f,-3.0718f,-2.8973f,-0.0175f,-2.8973f};
    const float HI[7] = { 2.8973f, 1.7628f, 2.8973f,-0.0698f, 2.8973f, 3.7525f, 2.8973f};

    float kp0[21], kp1[21];
    fk_eval(th0, kp0);
    fk_eval(th1, kp1);

    float* outA = out + (size_t)28 * Bn;   // all_angles (4,B,7)
    float* outK = out + (size_t)56 * Bn;   // all_kp     (4,B,7,3)

    if (v0) {
        #pragma unroll
        for (int j = 0; j < 7; j++)  outA[(size_t)be0*7 + j]  = th0[j];
        #pragma unroll
        for (int j = 0; j < 21; j++) outK[(size_t)be0*21 + j] = kp0[j];
    }
    if (v1) {
        #pragma unroll
        for (int j = 0; j < 7; j++)  outA[(size_t)be1v*7 + j]  = th1[j];
        #pragma unroll
        for (int j = 0; j < 21; j++) outK[(size_t)be1v*21 + j] = kp1[j];
    }

    for (int it = 0; it < 3; it++) {
        // ---- features for both elements ----
        float x0[28], x1[28];
        float mx0 = 0.f, mx1 = 0.f;
        #pragma unroll 1
        for (int e = 0; e < 2; e++) {
            const int bb = e ? be1v : be0;
            const float vm = e ? vm1 : vm0;
            const float* kp = e ? kp1 : kp0;
            const float* th = e ? th1 : th0;
            float* x = e ? x1 : x0;
            float Rm[9], Km[6], tv[3];
            #pragma unroll
            for (int j = 0; j < 9; j++) Rm[j] = Re[(size_t)bb*9 + j];
            #pragma unroll
            for (int j = 0; j < 6; j++) Km[j] = Kc[(size_t)bb*9 + j];
            #pragma unroll
            for (int j = 0; j < 3; j++) tv[j] = te[(size_t)bb*3 + j];
            float mx = 0.f;
            #pragma unroll
            for (int k = 0; k < 7; k++) {
                float px = kp[3*k], py = kp[3*k+1], pz = kp[3*k+2];
                float cx = Rm[0]*px + Rm[1]*py + Rm[2]*pz + tv[0];
                float cy = Rm[3]*px + Rm[4]*py + Rm[5]*pz + tv[1];
                float cz = Rm[6]*px + Rm[7]*py + Rm[8]*pz + tv[2];
                float z  = fmaxf(cz, 1e-6f);
                float inv = 1.0f / z;
                float nx = cx*inv, ny = cy*inv, nz = cz*inv;
                float u = Km[0]*nx + Km[1]*ny + Km[2]*nz;
                float v = Km[3]*nx + Km[4]*ny + Km[5]*nz;
                float dx = (tgt[(size_t)bb*14 + 2*k]   - u) * vm;
                float dy = (tgt[(size_t)bb*14 + 2*k+1] - v) * vm;
                x[2*k] = dx; x[2*k+1] = dy;
                float dm = sqrtf(dx*dx + dy*dy);
                x[21+k] = dm;
                mx = fmaxf(mx, dm);
            }
            #pragma unroll
            for (int j = 0; j < 7; j++) { x[14+j] = th[j]; mx = fmaxf(mx, fabsf(th[j])); }
            if (e) mx1 = mx; else mx0 = mx;
        }
        const float s0 = 64.f / (1.f + mx0);
        const float s1 = 64.f / (1.f + mx1);

        // ---- layer 1: 4 passes of 32 units (skewed), E=2; stage fp16 ----
        float sum1a = 0.f, sq1a = 0.f, sum1b = 0.f, sq1b = 0.f;
        #pragma unroll 1
        for (int pp = 0; pp < 4; pp++) {
            const int p = (pp + wskew) & 3;
            u64 acc0[16], acc1[16];
            const u64* pb1 = (const u64*)sb1 + p*16;
            #pragma unroll
            for (int i = 0; i < 16; i++) { u64 bi = pb1[i]; acc0[i] = bi; acc1[i] = bi; }
            const float* wbase = sW1 + p*32;
            #pragma unroll 4
            for (int k = 0; k < 28; k++) {
                u64 xa = pk2(x0[k], x0[k]);
                u64 xb = pk2(x1[k], x1[k]);
                const ulonglong2* wrow = (const ulonglong2*)(wbase + k*128);
                ulonglong2 w[8];
                #pragma unroll
                for (int i = 0; i < 8; i++) w[i] = wrow[i];
                #pragma unroll
                for (int i = 0; i < 8; i++) {
                    acc0[2*i]   = ffma2(xa, w[i].x, acc0[2*i]);
                    acc0[2*i+1] = ffma2(xa, w[i].y, acc0[2*i+1]);
                    acc1[2*i]   = ffma2(xb, w[i].x, acc1[2*i]);
                    acc1[2*i+1] = ffma2(xb, w[i].y, acc1[2*i+1]);
                }
            }
            #pragma unroll
            for (int i = 0; i < 16; i++) {
                float a0, a1; upk2(acc0[i], a0, a1);
                __half2 h2a = __float22half2_rn(make_float2(gelu_f(a0)*s0, gelu_f(a1)*s0));
                float2 ra = __half22float2(h2a);
                sum1a += ra.x + ra.y; sq1a += ra.x*ra.x + ra.y*ra.y;
                float c0, c1; upk2(acc1[i], c0, c1);
                __half2 h2b = __float22half2_rn(make_float2(gelu_f(c0)*s1, gelu_f(c1)*s1));
                float2 rb = __half22float2(h2b);
                sum1b += rb.x + rb.y; sq1b += rb.x*rb.x + rb.y*rb.y;
                sH[(p*16 + i)*TPB + tid] = make_uint2(h2_as_u32(h2a), h2_as_u32(h2b));
            }
        }
        float mu1a = sum1a * (1.f/128.f);
        float mu1b = sum1b * (1.f/128.f);
        float rstd1a = rsqrtf(sq1a*(1.f/128.f) - mu1a*mu1a + 1e-5f*s0*s0);
        float m1a    = -mu1a * rstd1a;
        float rstd1b = rsqrtf(sq1b*(1.f/128.f) - mu1b*mu1b + 1e-5f*s1*s1);
        float m1b    = -mu1b * rstd1b;

        // ---- layer 2: 4 passes of 32 units (skewed), E=2; batched loads + prefetch ----
        float sum2a = 0.f, sq2a = 0.f, sum2b = 0.f, sq2b = 0.f;
        float S0[7] = {0,0,0,0,0,0,0};
        float S1[7] = {0,0,0,0,0,0,0};
        #pragma unroll 1
        for (int pp = 0; pp < 4; pp++) {
            const int p = (pp + wskew) & 3;
            u64 acc0[16], acc1[16];
            #pragma unroll
            for (int i = 0; i < 16; i++) { acc0[i] = pk2(0.f,0.f); acc1[i] = pk2(0.f,0.f); }
            const float* wbase = sGW2 + p*32;
            uint2 hw = sH[tid];                       // j2 = 0 prefetch
            #pragma unroll 4
            for (int j2 = 0; j2 < 64; j2++) {
                // batch all 16 weight loads of this j2 up-front
                const ulonglong2* w0 = (const ulonglong2*)(wbase + (2*j2)*128);
                const ulonglong2* w1 = (const ulonglong2*)(wbase + (2*j2+1)*128);
                ulonglong2 wa[8], wb[8];
                #pragma unroll
                for (int i = 0; i < 8; i++) { wa[i] = w0[i]; wb[i] = w1[i]; }
                // prefetch next j2's h while weights are in flight
                uint2 hw_n = (j2 < 63) ? sH[(j2+1)*TPB + tid] : hw;
                float2 fa = __half22float2(u32_as_h2(hw.x));
                float2 fb = __half22float2(u32_as_h2(hw.y));
                u64 a0 = pk2(fa.x, fa.x);
                u64 a1 = pk2(fa.y, fa.y);
                u64 bb0 = pk2(fb.x, fb.x);
                u64 bb1 = pk2(fb.y, fb.y);
                #pragma unroll
                for (int i = 0; i < 8; i++) {
                    acc0[2*i]   = ffma2(a0, wa[i].x, acc0[2*i]);
                    acc0[2*i+1] = ffma2(a0, wa[i].y, acc0[2*i+1]);
                    acc1[2*i]   = ffma2(bb0, wa[i].x, acc1[2*i]);
                    acc1[2*i+1] = ffma2(bb0, wa[i].y, acc1[2*i+1]);
                }
                #pragma unroll
                for (int i = 0; i < 8; i++) {
                    acc0[2*i]   = ffma2(a1, wb[i].x, acc0[2*i]);
                    acc0[2*i+1] = ffma2(a1, wb[i].y, acc0[2*i+1]);
                    acc1[2*i]   = ffma2(bb1, wb[i].x, acc1[2*i]);
                    acc1[2*i+1] = ffma2(bb1, wb[i].y, acc1[2*i+1]);
                }
                hw = hw_n;
            }
            // epilogue: LN1 consts, gelu, stats, fused GEMM3 partials
            #pragma unroll
            for (int i = 0; i < 16; i++) {
                int u = p*32 + 2*i;
                float2 a2 = *(const float2*)(sA2 + u);
                float2 cb = *(const float2*)(sCB2 + u);
                const float4* g0p = (const float4*)(sGW3 + u*8);
                const float4* g1p = (const float4*)(sGW3 + (u+1)*8);
                float4 ga = g0p[0], gb = g0p[1], gc = g1p[0], gd = g1p[1];

                float t0, t1; upk2(acc0[i], t0, t1);
                float pre0 = fmaf(rstd1a, t0, fmaf(m1a, a2.x, cb.x));
                float pre1 = fmaf(rstd1a, t1, fmaf(m1a, a2.y, cb.y));
                float h0 = gelu_f(pre0), h1 = gelu_f(pre1);
                sum2a += h0 + h1; sq2a += h0*h0 + h1*h1;
                S0[0] = fmaf(h0, ga.x, fmaf(h1, gc.x, S0[0]));
                S0[1] = fmaf(h0, ga.y, fmaf(h1, gc.y, S0[1]));
                S0[2] = fmaf(h0, ga.z, fmaf(h1, gc.z, S0[2]));
                S0[3] = fmaf(h0, ga.w, fmaf(h1, gc.w, S0[3]));
                S0[4] = fmaf(h0, gb.x, fmaf(h1, gd.x, S0[4]));
                S0[5] = fmaf(h0, gb.y, fmaf(h1, gd.y, S0[5]));
                S0[6] = fmaf(h0, gb.z, fmaf(h1, gd.z, S0[6]));

                float u0, u1v; upk2(acc1[i], u0, u1v);
                float q0 = fmaf(rstd1b, u0, fmaf(m1b, a2.x, cb.x));
                float q1 = fmaf(rstd1b, u1v, fmaf(m1b, a2.y, cb.y));
                float k0 = gelu_f(q0), k1 = gelu_f(q1);
                sum2b += k0 + k1; sq2b += k0*k0 + k1*k1;
                S1[0] = fmaf(k0, ga.x, fmaf(k1, gc.x, S1[0]));
                S1[1] = fmaf(k0, ga.y, fmaf(k1, gc.y, S1[1]));
                S1[2] = fmaf(k0, ga.z, fmaf(k1, gc.z, S1[2]));
                S1[3] = fmaf(k0, ga.w, fmaf(k1, gc.w, S1[3]));
                S1[4] = fmaf(k0, gb.x, fmaf(k1, gd.x, S1[4]));
                S1[5] = fmaf(k0, gb.y, fmaf(k1, gd.y, S1[5]));
                S1[6] = fmaf(k0, gb.z, fmaf(k1, gd.z, S1[6]));
            }
        }
        float mu2a   = sum2a * (1.f/128.f);
        float rstd2a = rsqrtf(sq2a * (1.f/128.f) - mu2a*mu2a + 1e-5f);
        float m2a    = -mu2a * rstd2a;
        float mu2b   = sum2b * (1.f/128.f);
        float rstd2b = rsqrtf(sq2b * (1.f/128.f) - mu2b*mu2b + 1e-5f);
        float m2b    = -mu2b * rstd2b;

        float ss = ssv[it];
        #pragma unroll
        for (int j = 0; j < 7; j++) {
            float d0 = fmaf(rstd2a, S0[j], fmaf(m2a, sA3[j], sCB3[j]));
            float n0 = th0[j] + ss * d0;
            th0[j] = fminf(fmaxf(n0, LO[j]), HI[j]);
            float d1 = fmaf(rstd2b, S1[j], fmaf(m2b, sA3[j], sCB3[j]));
            float n1 = th1[j] + ss * d1;
            th1[j] = fminf(fmaxf(n1, LO[j]), HI[j]);
        }
        fk_eval(th0, kp0);
        fk_eval(th1, kp1);

        const size_t w = (size_t)(it + 1);
        if (v0) {
            #pragma unroll
            for (int j = 0; j < 7; j++)  outA[w*(size_t)Bn*7  + (size_t)be0*7  + j] = th0[j];
            #pragma unroll
            for (int j = 0; j < 21; j++) outK[w*(size_t)Bn*21 + (size_t)be0*21 + j] = kp0[j];
        }
        if (v1) {
            #pragma unroll
            for (int j = 0; j < 7; j++)  outA[w*(size_t)Bn*7  + (size_t)be1v*7  + j] = th1[j];
            #pragma unroll
            for (int j = 0; j < 21; j++) outK[w*(size_t)Bn*21 + (size_t)be1v*21 + j] = kp1[j];
        }
    }

    if (v0) {
        #pragma unroll
        for (int j = 0; j < 7; j++)  out[(size_t)be0*7 + j] = th0[j];
        #pragma unroll
        for (int j = 0; j < 21; j++) out[(size_t)7*Bn + (size_t)be0*21 + j] = kp0[j];
    }
    if (v1) {
        #pragma unroll
        for (int j = 0; j < 7; j++)  out[(size_t)be1v*7 + j] = th1[j];
        #pragma unroll
        for (int j = 0; j < 21; j++) out[(size_t)7*Bn + (size_t)be1v*21 + j] = kp1[j];
    }
}

extern "C" void kernel_launch(void* const* d_in, const int* in_sizes, int n_in,
                              void* d_out, int out_size)
{
    const float* ang  = (const float*)d_in[0];
    const float* tgt  = (const float*)d_in[1];
    const float* Kc   = (const float*)d_in[2];
    const float* Re   = (const float*)d_in[4];
    const float* te   = (const float*)d_in[5];
    const int*   vmk  = (const int*)d_in[6];
    const float* W1   = (const float*)d_in[7];
    const float* b1   = (const float*)d_in[8];
    const float* g1   = (const float*)d_in[9];
    const float* be1  = (const float*)d_in[10];
    const float* W2   = (const float*)d_in[11];
    const float* b2   = (const float*)d_in[12];
    const float* g2   = (const float*)d_in[13];
    const float* be2  = (const float*)d_in[14];
    const float* W3   = (const float*)d_in[15];
    const float* b3   = (const float*)d_in[16];
    const float* slog = (const float*)d_in[17];

    const int Bn = in_sizes[0] / 7;
    const size_t smem = (size_t)SMEM_BYTES;

    cudaFuncSetAttribute(irm_kernel, cudaFuncAttributeMaxDynamicSharedMemorySize, (int)smem);

    const int grid = (Bn + EPB - 1) / EPB;
    irm_kernel<<<grid, TPB, smem>>>(ang, tgt, Kc, Re, te, vmk,
                                    W1, b1, g1, be1, W2, b2, g2, be2, W3, b3,
                                    slog, (float*)d_out, Bn);
}

// round 15
// speedup vs baseline: 1.2013x; 1.0477x over previous
#include <cuda_runtime.h>
#include <cuda_fp16.h>
#include <math.h>

#define TPB 256
#define EPB 512   // 2 elements per thread

typedef unsigned long long u64;

__device__ __forceinline__ u64 pk2(float x, float y) {
    u64 r; asm("mov.b64 %0, {%1,%2};" : "=l"(r) : "f"(x), "f"(y)); return r;
}
__device__ __forceinline__ void upk2(u64 v, float& x, float& y) {
    asm("mov.b64 {%0,%1}, %2;" : "=f"(x), "=f"(y) : "l"(v));
}
__device__ __forceinline__ u64 ffma2(u64 a, u64 b, u64 c) {
    u64 d; asm("fma.rn.f32x2 %0, %1, %2, %3;" : "=l"(d) : "l"(a), "l"(b), "l"(c)); return d;
}
// GELU with A&S 7.1.26 erf (max abs err 1.5e-7; RCP/EX2 on MUFU pipe, off fma pipe)
__device__ __forceinline__ float gelu_f(float x) {
    float z  = fabsf(x) * 0.70710678118654752440f;
    float t  = __fdividef(1.0f, fmaf(0.3275911f, z, 1.0f));              // MUFU.RCP
    float p  = t * fmaf(t, fmaf(t, fmaf(t, fmaf(t, 1.061405429f,
                 -1.453152027f), 1.421413741f), -0.284496736f), 0.254829592f);
    float e  = __expf(-z * z);                                            // MUFU.EX2
    float er = fmaf(-p, e, 1.0f);                                         // erf(|z|)
    float erfv = copysignf(er, x);
    return 0.5f * x * (1.0f + erfv);
}
__device__ __forceinline__ unsigned h2_as_u32(__half2 h) {
    return *reinterpret_cast<unsigned*>(&h);
}
__device__ __forceinline__ __half2 u32_as_h2(unsigned u) {
    return *reinterpret_cast<__half2*>(&u);
}

// FK for the 7-DOF Panda chain -> 7 keypoints
__device__ __forceinline__ void fk_eval(const float th[7], float kp[21]) {
    const float FR[7][9] = {
        {1,0,0,  0,1,0,   0,0,1},
        {1,0,0,  0,0,1,   0,-1,0},
        {1,0,0,  0,0,-1,  0,1,0},
        {1,0,0,  0,0,-1,  0,1,0},
        {1,0,0,  0,0,1,   0,-1,0},
        {1,0,0,  0,0,-1,  0,1,0},
        {1,0,0,  0,0,-1,  0,1,0}
    };
    const float FT[7][3] = {
        {0.f,0.f,0.333f},{0.f,0.f,0.f},{0.f,-0.316f,0.f},{0.0825f,0.f,0.f},
        {-0.0825f,0.384f,0.f},{0.f,0.f,0.f},{0.088f,0.f,0.f}
    };
    float r[9] = {1,0,0, 0,1,0, 0,0,1};
    float t[3] = {0,0,0};
    kp[0] = 0.f; kp[1] = 0.f; kp[2] = 0.f;
    int w = 3;
    #pragma unroll
    for (int i = 0; i < 7; i++) {
        float s, c; __sincosf(th[i], &s, &c);
        float sr[9];
        sr[0] =  FR[i][0]*c + FR[i][1]*s;  sr[1] = -FR[i][0]*s + FR[i][1]*c;  sr[2] = FR[i][2];
        sr[3] =  FR[i][3]*c + FR[i][4]*s;  sr[4] = -FR[i][3]*s + FR[i][4]*c;  sr[5] = FR[i][5];
        sr[6] =  FR[i][6]*c + FR[i][7]*s;  sr[7] = -FR[i][6]*s + FR[i][7]*c;  sr[8] = FR[i][8];
        float nt0 = r[0]*FT[i][0] + r[1]*FT[i][1] + r[2]*FT[i][2] + t[0];
        float nt1 = r[3]*FT[i][0] + r[4]*FT[i][1] + r[5]*FT[i][2] + t[1];
        float nt2 = r[6]*FT[i][0] + r[7]*FT[i][1] + r[8]*FT[i][2] + t[2];
        float nr[9];
        #pragma unroll
        for (int a = 0; a < 3; a++)
            #pragma unroll
            for (int bq = 0; bq < 3; bq++)
                nr[a*3+bq] = r[a*3+0]*sr[bq] + r[a*3+1]*sr[3+bq] + r[a*3+2]*sr[6+bq];
        #pragma unroll
        for (int q = 0; q < 9; q++) r[q] = nr[q];
        t[0] = nt0; t[1] = nt1; t[2] = nt2;
        if (i == 1 || i == 2 || i == 3 || i == 5 || i == 6) {
            kp[w] = t[0]; kp[w+1] = t[1]; kp[w+2] = t[2]; w += 3;
        }
    }
    kp[18] = t[0] + r[2]*0.107f;
    kp[19] = t[1] + r[5]*0.107f;
    kp[20] = t[2] + r[8]*0.107f;
}

// ---- smem float offsets ----
#define OFF_W1    0                    // 28*128 raw
#define OFF_GW2   3584                 // 128*128 (g1-scaled W2)
#define OFF_GW3   (OFF_GW2 + 16384)    // 128*8 (g2-scaled W3, padded)
#define OFF_B1    (OFF_GW3 + 1024)     // 128
#define OFF_G1    (OFF_B1 + 128)
#define OFF_BE1   (OFF_G1 + 128)
#define OFF_A2    (OFF_BE1 + 128)      // 128
#define OFF_CB2   (OFF_A2 + 128)       // 128
#define OFF_A3    (OFF_CB2 + 128)      // 8
#define OFF_CB3   (OFF_A3 + 8)         // 8
#define OFF_H     (OFF_CB3 + 8)        // uint2 staging: 64 pairs * TPB * 8B
#define SMEM_BYTES (OFF_H * 4 + 64 * TPB * 8)

__global__ void __launch_bounds__(TPB, 1)
irm_kernel(const float* __restrict__ ang, const float* __restrict__ tgt,
           const float* __restrict__ Kc,  const float* __restrict__ Re,
           const float* __restrict__ te,  const int* __restrict__ vmk,
           const float* __restrict__ W1,  const float* __restrict__ b1,
           const float* __restrict__ g1,  const float* __restrict__ be1,
           const float* __restrict__ W2,  const float* __restrict__ b2,
           const float* __restrict__ g2,  const float* __restrict__ be2,
           const float* __restrict__ W3,  const float* __restrict__ b3,
           const float* __restrict__ slog, float* __restrict__ out, int Bn)
{
    extern __shared__ float sm[];
    float* sW1  = sm + OFF_W1;
    float* sGW2 = sm + OFF_GW2;
    float* sGW3 = sm + OFF_GW3;
    float* sb1  = sm + OFF_B1;
    float* sg1  = sm + OFF_G1;
    float* sbe1 = sm + OFF_BE1;
    float* sA2  = sm + OFF_A2;
    float* sCB2 = sm + OFF_CB2;
    float* sA3  = sm + OFF_A3;
    float* sCB3 = sm + OFF_CB3;
    uint2* sH   = (uint2*)(sm + OFF_H);   // [64 pairs][TPB], both elems packed

    const int tid = threadIdx.x;
    const int wskew = ((tid >> 7) & 1) * 2;

    // ---- phase 1: raw weight loads + GW3 (g2-scaled W3) ----
    for (int i = tid; i < 3584;  i += TPB) sW1[i] = W1[i];
    for (int i = tid; i < 16384; i += TPB) sGW2[i] = W2[i];   // raw for now
    for (int i = tid; i < 1024;  i += TPB) {
        int k = i >> 3, j = i & 7;
        sGW3[i] = (j < 7) ? g2[k] * W3[k*7 + j] : 0.f;
    }
    if (tid < 128) {
        sb1[tid] = b1[tid]; sg1[tid] = g1[tid]; sbe1[tid] = be1[tid];
    }
    __syncthreads();

    // ---- phase 2: fold LN1 into layer-2 constants ----
    if (tid < 128) {
        float a2 = 0.f, cb2 = 0.f;
        for (int k = 0; k < 128; k++) {
            float w = sGW2[k*128 + tid];
            a2  += sg1[k]  * w;
            cb2 += sbe1[k] * w;
        }
        sA2[tid]  = a2;
        sCB2[tid] = cb2 + b2[tid];
    } else if (tid < 136) {
        int c = tid - 128;
        float a3 = 0.f, cb3 = 0.f;
        if (c < 7) {
            for (int k = 0; k < 128; k++) {
                a3  += sGW3[k*8 + c];
                cb3 += be2[k] * W3[k*7 + c];
            }
            cb3 += b3[c];
        }
        sA3[c]  = a3;
        sCB3[c] = cb3;
    }
    __syncthreads();

    // ---- phase 3: scale W2 in place by g1 ----
    for (int i = tid; i < 16384; i += TPB) sGW2[i] *= sg1[i >> 7];
    __syncthreads();

    // ---- two elements per thread ----
    const int b0r = blockIdx.x * EPB + tid;
    const int b1r = b0r + TPB;
    const bool v0 = (b0r < Bn), v1 = (b1r < Bn);
    const int be0  = v0 ? b0r : (Bn - 1);
    const int be1v = v1 ? b1r : (Bn - 1);

    float th0[7], th1[7];
    #pragma unroll
    for (int j = 0; j < 7; j++) { th0[j] = ang[(size_t)be0*7 + j]; th1[j] = ang[(size_t)be1v*7 + j]; }
    const float vm0 = (vmk[be0]  != 0) ? 1.f : 0.f;
    const float vm1 = (vmk[be1v] != 0) ? 1.f : 0.f;
    float ssv[3];
    #pragma unroll
    for (int j = 0; j < 3; j++) ssv[j] = 1.f / (1.f + expf(-slog[j]));

    const float LO[7] = {-2.8973f,-1.7628f,-2.8973f,-3.0718f,-2.8973f,-0.0175f,-2.8973f};
    const float HI[7] = { 2.8973f, 1.7628f, 2.8973f,-0.0698f, 2.8973f, 3.7525f, 2.8973f};

    float kp0[21], kp1[21];
    fk_eval(th0, kp0);
    fk_eval(th1, kp1);

    float* outA = out + (size_t)28 * Bn;   // all_angles (4,B,7)
    float* outK = out + (size_t)56 * Bn;   // all_kp     (4,B,7,3)

    if (v0) {
        #pragma unroll
        for (int j = 0; j < 7; j++)  outA[(size_t)be0*7 + j]  = th0[j];
        #pragma unroll
        for (int j = 0; j < 21; j++) outK[(size_t)be0*21 + j] = kp0[j];
    }
    if (v1) {
        #pragma unroll
        for (int j = 0; j < 7; j++)  outA[(size_t)be1v*7 + j]  = th1[j];
        #pragma unroll
        for (int j = 0; j < 21; j++) outK[(size_t)be1v*21 + j] = kp1[j];
    }

    for (int it = 0; it < 3; it++) {
        // ---- features for both elements ----
        float x0[28], x1[28];
        float mx0 = 0.f, mx1 = 0.f;
        #pragma unroll 1
        for (int e = 0; e < 2; e++) {
            const int bb = e ? be1v : be0;
            const float vm = e ? vm1 : vm0;
            const float* kp = e ? kp1 : kp0;
            const float* th = e ? th1 : th0;
            float* x = e ? x1 : x0;
            float Rm[9], Km[6], tv[3];
            #pragma unroll
            for (int j = 0; j < 9; j++) Rm[j] = Re[(size_t)bb*9 + j];
            #pragma unroll
            for (int j = 0; j < 6; j++) Km[j] = Kc[(size_t)bb*9 + j];
            #pragma unroll
            for (int j = 0; j < 3; j++) tv[j] = te[(size_t)bb*3 + j];
            float mx = 0.f;
            #pragma unroll
            for (int k = 0; k < 7; k++) {
                float px = kp[3*k], py = kp[3*k+1], pz = kp[3*k+2];
                float cx = Rm[0]*px + Rm[1]*py + Rm[2]*pz + tv[0];
                float cy = Rm[3]*px + Rm[4]*py + Rm[5]*pz + tv[1];
                float cz = Rm[6]*px + Rm[7]*py + Rm[8]*pz + tv[2];
                float z  = fmaxf(cz, 1e-6f);
                float inv = 1.0f / z;
                float nx = cx*inv, ny = cy*inv, nz = cz*inv;
                float u = Km[0]*nx + Km[1]*ny + Km[2]*nz;
                float v = Km[3]*nx + Km[4]*ny + Km[5]*nz;
                float dx = (tgt[(size_t)bb*14 + 2*k]   - u) * vm;
                float dy = (tgt[(size_t)bb*14 + 2*k+1] - v) * vm;
                x[2*k] = dx; x[2*k+1] = dy;
                float dm = sqrtf(dx*dx + dy*dy);
                x[21+k] = dm;
                mx = fmaxf(mx, dm);
            }
            #pragma unroll
            for (int j = 0; j < 7; j++) { x[14+j] = th[j]; mx = fmaxf(mx, fabsf(th[j])); }
            if (e) mx1 = mx; else mx0 = mx;
        }
        const float s0 = 64.f / (1.f + mx0);
        const float s1 = 64.f / (1.f + mx1);

        // ---- layer 1: 4 passes of 32 units (skewed), E=2; stage fp16 ----
        float sum1a = 0.f, sq1a = 0.f, sum1b = 0.f, sq1b = 0.f;
        #pragma unroll 1
        for (int pp = 0; pp < 4; pp++) {
            const int p = (pp + wskew) & 3;
            u64 acc0[16], acc1[16];
            const u64* pb1 = (const u64*)sb1 + p*16;
            #pragma unroll
            for (int i = 0; i < 16; i++) { u64 bi = pb1[i]; acc0[i] = bi; acc1[i] = bi; }
            const float* wbase = sW1 + p*32;
            #pragma unroll 4
            for (int k = 0; k < 28; k++) {
                u64 xa = pk2(x0[k], x0[k]);
                u64 xb = pk2(x1[k], x1[k]);
                const ulonglong2* wrow = (const ulonglong2*)(wbase + k*128);
                ulonglong2 w[8];
                #pragma unroll
                for (int i = 0; i < 8; i++) w[i] = wrow[i];
                #pragma unroll
                for (int i = 0; i < 8; i++) {
                    acc0[2*i]   = ffma2(xa, w[i].x, acc0[2*i]);
                    acc0[2*i+1] = ffma2(xa, w[i].y, acc0[2*i+1]);
                    acc1[2*i]   = ffma2(xb, w[i].x, acc1[2*i]);
                    acc1[2*i+1] = ffma2(xb, w[i].y, acc1[2*i+1]);
                }
            }
            #pragma unroll
            for (int i = 0; i < 16; i++) {
                float a0, a1; upk2(acc0[i], a0, a1);
                __half2 h2a = __float22half2_rn(make_float2(gelu_f(a0)*s0, gelu_f(a1)*s0));
                float2 ra = __half22float2(h2a);
                sum1a += ra.x + ra.y; sq1a += ra.x*ra.x + ra.y*ra.y;
                float c0, c1; upk2(acc1[i], c0, c1);
                __half2 h2b = __float22half2_rn(make_float2(gelu_f(c0)*s1, gelu_f(c1)*s1));
                float2 rb = __half22float2(h2b);
                sum1b += rb.x + rb.y; sq1b += rb.x*rb.x + rb.y*rb.y;
                sH[(p*16 + i)*TPB + tid] = make_uint2(h2_as_u32(h2a), h2_as_u32(h2b));
            }
        }
        float mu1a = sum1a * (1.f/128.f);
        float mu1b = sum1b * (1.f/128.f);
        float rstd1a = rsqrtf(sq1a*(1.f/128.f) - mu1a*mu1a + 1e-5f*s0*s0);
        float m1a    = -mu1a * rstd1a;
        float rstd1b = rsqrtf(sq1b*(1.f/128.f) - mu1b*mu1b + 1e-5f*s1*s1);
        float m1b    = -mu1b * rstd1b;

        // ---- layer 2: 4 passes of 32 units (skewed), E=2; batched loads + prefetch ----
        float sum2a = 0.f, sq2a = 0.f, sum2b = 0.f, sq2b = 0.f;
        float S0[7] = {0,0,0,0,0,0,0};
        float S1[7] = {0,0,0,0,0,0,0};
        #pragma unroll 1
        for (int pp = 0; pp < 4; pp++) {
            const int p = (pp + wskew) & 3;
            u64 acc0[16], acc1[16];
            #pragma unroll
            for (int i = 0; i < 16; i++) { acc0[i] = pk2(0.f,0.f); acc1[i] = pk2(0.f,0.f); }
            const float* wbase = sGW2 + p*32;
            uint2 hw = sH[tid];
            #pragma unroll 4
            for (int j2 = 0; j2 < 64; j2++) {
                const ulonglong2* w0 = (const ulonglong2*)(wbase + (2*j2)*128);
                const ulonglong2* w1 = (const ulonglong2*)(wbase + (2*j2+1)*128);
                ulonglong2 wa[8], wb[8];
                #pragma unroll
                for (int i = 0; i < 8; i++) { wa[i] = w0[i]; wb[i] = w1[i]; }
                uint2 hw_n = (j2 < 63) ? sH[(j2+1)*TPB + tid] : hw;
                float2 fa = __half22float2(u32_as_h2(hw.x));
                float2 fb = __half22float2(u32_as_h2(hw.y));
                u64 a0 = pk2(fa.x, fa.x);
                u64 a1 = pk2(fa.y, fa.y);
                u64 bb0 = pk2(fb.x, fb.x);
                u64 bb1 = pk2(fb.y, fb.y);
                #pragma unroll
                for (int i = 0; i < 8; i++) {
                    acc0[2*i]   = ffma2(a0, wa[i].x, acc0[2*i]);
                    acc0[2*i+1] = ffma2(a0, wa[i].y, acc0[2*i+1]);
                    acc1[2*i]   = ffma2(bb0, wa[i].x, acc1[2*i]);
                    acc1[2*i+1] = ffma2(bb0, wa[i].y, acc1[2*i+1]);
                }
                #pragma unroll
                for (int i = 0; i < 8; i++) {
                    acc0[2*i]   = ffma2(a1, wb[i].x, acc0[2*i]);
                    acc0[2*i+1] = ffma2(a1, wb[i].y, acc0[2*i+1]);
                    acc1[2*i]   = ffma2(bb1, wb[i].x, acc1[2*i]);
                    acc1[2*i+1] = ffma2(bb1, wb[i].y, acc1[2*i+1]);
                }
                hw = hw_n;
            }
            // epilogue: LN1 consts, gelu, stats, fused GEMM3 partials
            #pragma unroll
            for (int i = 0; i < 16; i++) {
                int u = p*32 + 2*i;
                float2 a2 = *(const float2*)(sA2 + u);
                float2 cb = *(const float2*)(sCB2 + u);
                const float4* g0p = (const float4*)(sGW3 + u*8);
                const float4* g1p = (const float4*)(sGW3 + (u+1)*8);
                float4 ga = g0p[0], gb = g0p[1], gc = g1p[0], gd = g1p[1];

                float t0, t1; upk2(acc0[i], t0, t1);
                float pre0 = fmaf(rstd1a, t0, fmaf(m1a, a2.x, cb.x));
                float pre1 = fmaf(rstd1a, t1, fmaf(m1a, a2.y, cb.y));
                float h0 = gelu_f(pre0), h1 = gelu_f(pre1);
                sum2a += h0 + h1; sq2a += h0*h0 + h1*h1;
                S0[0] = fmaf(h0, ga.x, fmaf(h1, gc.x, S0[0]));
                S0[1] = fmaf(h0, ga.y, fmaf(h1, gc.y, S0[1]));
                S0[2] = fmaf(h0, ga.z, fmaf(h1, gc.z, S0[2]));
                S0[3] = fmaf(h0, ga.w, fmaf(h1, gc.w, S0[3]));
                S0[4] = fmaf(h0, gb.x, fmaf(h1, gd.x, S0[4]));
                S0[5] = fmaf(h0, gb.y, fmaf(h1, gd.y, S0[5]));
                S0[6] = fmaf(h0, gb.z, fmaf(h1, gd.z, S0[6]));

                float u0, u1v; upk2(acc1[i], u0, u1v);
                float q0 = fmaf(rstd1b, u0, fmaf(m1b, a2.x, cb.x));
                float q1 = fmaf(rstd1b, u1v, fmaf(m1b, a2.y, cb.y));
                float k0 = gelu_f(q0), k1 = gelu_f(q1);
                sum2b += k0 + k1; sq2b += k0*k0 + k1*k1;
                S1[0] = fmaf(k0, ga.x, fmaf(k1, gc.x, S1[0]));
                S1[1] = fmaf(k0, ga.y, fmaf(k1, gc.y, S1[1]));
                S1[2] = fmaf(k0, ga.z, fmaf(k1, gc.z, S1[2]));
                S1[3] = fmaf(k0, ga.w, fmaf(k1, gc.w, S1[3]));
                S1[4] = fmaf(k0, gb.x, fmaf(k1, gd.x, S1[4]));
                S1[5] = fmaf(k0, gb.y, fmaf(k1, gd.y, S1[5]));
                S1[6] = fmaf(k0, gb.z, fmaf(k1, gd.z, S1[6]));
            }
        }
        float mu2a   = sum2a * (1.f/128.f);
        float rstd2a = rsqrtf(sq2a * (1.f/128.f) - mu2a*mu2a + 1e-5f);
        float m2a    = -mu2a * rstd2a;
        float mu2b   = sum2b * (1.f/128.f);
        float rstd2b = rsqrtf(sq2b * (1.f/128.f) - mu2b*mu2b + 1e-5f);
        float m2b    = -mu2b * rstd2b;

        float ss = ssv[it];
        #pragma unroll
        for (int j = 0; j < 7; j++) {
            float d0 = fmaf(rstd2a, S0[j], fmaf(m2a, sA3[j], sCB3[j]));
            float n0 = th0[j] + ss * d0;
            th0[j] = fminf(fmaxf(n0, LO[j]), HI[j]);
            float d1 = fmaf(rstd2b, S1[j], fmaf(m2b, sA3[j], sCB3[j]));
            float n1 = th1[j] + ss * d1;
            th1[j] = fminf(fmaxf(n1, LO[j]), HI[j]);
        }
        fk_eval(th0, kp0);
        fk_eval(th1, kp1);

        const size_t w = (size_t)(it + 1);
        if (v0) {
            #pragma unroll
            for (int j = 0; j < 7; j++)  outA[w*(size_t)Bn*7  + (size_t)be0*7  + j] = th0[j];
            #pragma unroll
            for (int j = 0; j < 21; j++) outK[w*(size_t)Bn*21 + (size_t)be0*21 + j] = kp0[j];
        }
        if (v1) {
            #pragma unroll
            for (int j = 0; j < 7; j++)  outA[w*(size_t)Bn*7  + (size_t)be1v*7  + j] = th1[j];
            #pragma unroll
            for (int j = 0; j < 21; j++) outK[w*(size_t)Bn*21 + (size_t)be1v*21 + j] = kp1[j];
        }
    }

    if (v0) {
        #pragma unroll
        for (int j = 0; j < 7; j++)  out[(size_t)be0*7 + j] = th0[j];
        #pragma unroll
        for (int j = 0; j < 21; j++) out[(size_t)7*Bn + (size_t)be0*21 + j] = kp0[j];
    }
    if (v1) {
        #pragma unroll
        for (int j = 0; j < 7; j++)  out[(size_t)be1v*7 + j] = th1[j];
        #pragma unroll
        for (int j = 0; j < 21; j++) out[(size_t)7*Bn + (size_t)be1v*21 + j] = kp1[j];
    }
}

extern "C" void kernel_launch(void* const* d_in, const int* in_sizes, int n_in,
                              void* d_out, int out_size)
{
    const float* ang  = (const float*)d_in[0];
    const float* tgt  = (const float*)d_in[1];
    const float* Kc   = (const float*)d_in[2];
    const float* Re   = (const float*)d_in[4];
    const float* te   = (const float*)d_in[5];
    const int*   vmk  = (const int*)d_in[6];
    const float* W1   = (const float*)d_in[7];
    const float* b1   = (const float*)d_in[8];
    const float* g1   = (const float*)d_in[9];
    const float* be1  = (const float*)d_in[10];
    const float* W2   = (const float*)d_in[11];
    const float* b2   = (const float*)d_in[12];
    const float* g2   = (const float*)d_in[13];
    const float* be2  = (const float*)d_in[14];
    const float* W3   = (const float*)d_in[15];
    const float* b3   = (const float*)d_in[16];
    const float* slog = (const float*)d_in[17];

    const int Bn = in_sizes[0] / 7;
    const size_t smem = (size_t)SMEM_BYTES;

    cudaFuncSetAttribute(irm_kernel, cudaFuncAttributeMaxDynamicSharedMemorySize, (int)smem);

    const int grid = (Bn + EPB - 1) / EPB;
    irm_kernel<<<grid, TPB, smem>>>(ang, tgt, Kc, Re, te, vmk,
                                    W1, b1, g1, be1, W2, b2, g2, be2, W3, b3,
                                    slog, (float*)d_out, Bn);
}

// round 16
// speedup vs baseline: 1.7859x; 1.4866x over previous
#include <cuda_runtime.h>
#include <cuda_fp16.h>
#include <math.h>
#include <stdint.h>

#define TPB 256
#define EPB 512   // 64 elements per warp, 8 warps

typedef unsigned long long u64;

__device__ __forceinline__ u64 pk2(float x, float y) {
    u64 r; asm("mov.b64 %0, {%1,%2};" : "=l"(r) : "f"(x), "f"(y)); return r;
}
__device__ __forceinline__ void upk2(u64 v, float& x, float& y) {
    asm("mov.b64 {%0,%1}, %2;" : "=f"(x), "=f"(y) : "l"(v));
}
__device__ __forceinline__ u64 ffma2(u64 a, u64 b, u64 c) {
    u64 d; asm("fma.rn.f32x2 %0, %1, %2, %3;" : "=l"(d) : "l"(a), "l"(b), "l"(c)); return d;
}
// GELU with A&S erf (MUFU RCP/EX2; max abs err 1.5e-7)
__device__ __forceinline__ float gelu_f(float x) {
    float z  = fabsf(x) * 0.70710678118654752440f;
    float t  = __fdividef(1.0f, fmaf(0.3275911f, z, 1.0f));
    float p  = t * fmaf(t, fmaf(t, fmaf(t, fmaf(t, 1.061405429f,
                 -1.453152027f), 1.421413741f), -0.284496736f), 0.254829592f);
    float e  = __expf(-z * z);
    float er = fmaf(-p, e, 1.0f);
    return 0.5f * x * (1.0f + copysignf(er, x));
}
__device__ __forceinline__ unsigned h2_as_u32(__half2 h) {
    return *reinterpret_cast<unsigned*>(&h);
}

#define LDSM4(r0,r1,r2,r3,addr) \
    asm volatile("ldmatrix.sync.aligned.m8n8.x4.shared.b16 {%0,%1,%2,%3}, [%4];" \
        : "=r"(r0),"=r"(r1),"=r"(r2),"=r"(r3) : "r"(addr))
#define LDSM2(r0,r1,addr) \
    asm volatile("ldmatrix.sync.aligned.m8n8.x2.shared.b16 {%0,%1}, [%2];" \
        : "=r"(r0),"=r"(r1) : "r"(addr))
#define MMA16816(c0,c1,c2,c3,a0,a1,a2,a3,b0,b1) \
    asm volatile("mma.sync.aligned.m16n8k16.row.col.f32.f16.f16.f32 " \
        "{%0,%1,%2,%3}, {%4,%5,%6,%7}, {%8,%9}, {%0,%1,%2,%3};" \
        : "+f"(c0),"+f"(c1),"+f"(c2),"+f"(c3) \
        : "r"(a0),"r"(a1),"r"(a2),"r"(a3),"r"(b0),"r"(b1))

// FK for the 7-DOF Panda chain -> 7 keypoints
__device__ __forceinline__ void fk_eval(const float th[7], float kp[21]) {
    const float FR[7][9] = {
        {1,0,0,  0,1,0,   0,0,1},
        {1,0,0,  0,0,1,   0,-1,0},
        {1,0,0,  0,0,-1,  0,1,0},
        {1,0,0,  0,0,-1,  0,1,0},
        {1,0,0,  0,0,1,   0,-1,0},
        {1,0,0,  0,0,-1,  0,1,0},
        {1,0,0,  0,0,-1,  0,1,0}
    };
    const float FT[7][3] = {
        {0.f,0.f,0.333f},{0.f,0.f,0.f},{0.f,-0.316f,0.f},{0.0825f,0.f,0.f},
        {-0.0825f,0.384f,0.f},{0.f,0.f,0.f},{0.088f,0.f,0.f}
    };
    float r[9] = {1,0,0, 0,1,0, 0,0,1};
    float t[3] = {0,0,0};
    kp[0] = 0.f; kp[1] = 0.f; kp[2] = 0.f;
    int w = 3;
    #pragma unroll
    for (int i = 0; i < 7; i++) {
        float s, c; __sincosf(th[i], &s, &c);
        float sr[9];
        sr[0] =  FR[i][0]*c + FR[i][1]*s;  sr[1] = -FR[i][0]*s + FR[i][1]*c;  sr[2] = FR[i][2];
        sr[3] =  FR[i][3]*c + FR[i][4]*s;  sr[4] = -FR[i][3]*s + FR[i][4]*c;  sr[5] = FR[i][5];
        sr[6] =  FR[i][6]*c + FR[i][7]*s;  sr[7] = -FR[i][6]*s + FR[i][7]*c;  sr[8] = FR[i][8];
        float nt0 = r[0]*FT[i][0] + r[1]*FT[i][1] + r[2]*FT[i][2] + t[0];
        float nt1 = r[3]*FT[i][0] + r[4]*FT[i][1] + r[5]*FT[i][2] + t[1];
        float nt2 = r[6]*FT[i][0] + r[7]*FT[i][1] + r[8]*FT[i][2] + t[2];
        float nr[9];
        #pragma unroll
        for (int a = 0; a < 3; a++)
            #pragma unroll
            for (int bq = 0; bq < 3; bq++)
                nr[a*3+bq] = r[a*3+0]*sr[bq] + r[a*3+1]*sr[3+bq] + r[a*3+2]*sr[6+bq];
        #pragma unroll
        for (int q = 0; q < 9; q++) r[q] = nr[q];
        t[0] = nt0; t[1] = nt1; t[2] = nt2;
        if (i == 1 || i == 2 || i == 3 || i == 5 || i == 6) {
            kp[w] = t[0]; kp[w+1] = t[1]; kp[w+2] = t[2]; w += 3;
        }
    }
    kp[18] = t[0] + r[2]*0.107f;
    kp[19] = t[1] + r[5]*0.107f;
    kp[20] = t[2] + r[8]*0.107f;
}

// ---- smem layout (bytes) ----
// B_HI [128n][272B] | B_LO | H 8 warps x 64 x 272B | W1 | GW3 | vecs
#define B_HI_B 0
#define B_LO_B 34816
#define H_B    69632            // + w*17408
#define W1_F   52224            // byte 208896
#define GW3_F  55808            // byte 223232
#define B1_F   56832
#define A2_F   56960
#define CB2_F  57088
#define A3_F   57216
#define CB3_F  57224
#define G1_F   57232
#define BE1_F  57360
#define SMEM_FLOATS 57488       // 229,952 bytes

__global__ void __launch_bounds__(TPB, 1)
irm_kernel(const float* __restrict__ ang, const float* __restrict__ tgt,
           const float* __restrict__ Kc,  const float* __restrict__ Re,
           const float* __restrict__ te,  const int* __restrict__ vmk,
           const float* __restrict__ W1,  const float* __restrict__ b1,
           const float* __restrict__ g1,  const float* __restrict__ be1,
           const float* __restrict__ W2,  const float* __restrict__ b2,
           const float* __restrict__ g2,  const float* __restrict__ be2,
           const float* __restrict__ W3,  const float* __restrict__ b3,
           const float* __restrict__ slog, float* __restrict__ out, int Bn)
{
    extern __shared__ float sm[];
    char*  smc  = (char*)sm;
    float* sW1  = sm + W1_F;
    float* sGW3 = sm + GW3_F;
    float* sb1  = sm + B1_F;
    float* sA2  = sm + A2_F;
    float* sCB2 = sm + CB2_F;
    float* sA3  = sm + A3_F;
    float* sCB3 = sm + CB3_F;
    float* sG1  = sm + G1_F;
    float* sBE1 = sm + BE1_F;

    uint32_t smem_u32;
    asm("{ .reg .u64 t; cvta.to.shared.u64 t, %1; cvt.u32.u64 %0, t; }" : "=r"(smem_u32) : "l"(sm));

    const int tid = threadIdx.x;
    const int w   = tid >> 5;        // warp id
    const int t   = tid & 31;        // lane

    // ---- init ----
    for (int i = tid; i < 3584; i += TPB) sW1[i] = W1[i];
    if (tid < 128) { sG1[tid] = g1[tid]; sBE1[tid] = be1[tid]; sb1[tid] = b1[tid]; }
    for (int i = tid; i < 1024; i += TPB) {
        int k = i >> 3, j = i & 7;
        sGW3[i] = (j < 7) ? g2[k] * W3[k*7 + j] : 0.f;
    }
    __syncthreads();
    // B build: B[n][k] = g1[k]*W2[k][n], fp16 hi + lo, row stride 272B
    for (int i = tid; i < 16384; i += TPB) {
        int k = i >> 7, n = i & 127;
        float wv = sG1[k] * W2[i];
        __half hi = __float2half_rn(wv);
        __half lo = __float2half_rn(wv - __half2float(hi));
        int off = n*272 + k*2;
        *(__half*)(smc + B_HI_B + off) = hi;
        *(__half*)(smc + B_LO_B + off) = lo;
    }
    // LN folds (gmem W2 column reads, coalesced across threads)
    if (tid < 128) {
        float a2 = 0.f, cb2 = 0.f;
        for (int k = 0; k < 128; k++) {
            float wv = W2[k*128 + tid];
            a2  += sG1[k]  * wv;
            cb2 += sBE1[k] * wv;
        }
        sA2[tid]  = a2;
        sCB2[tid] = cb2 + b2[tid];
    } else if (tid < 136) {
        int c = tid - 128;
        float a3 = 0.f, cb3 = 0.f;
        if (c < 7) {
            for (int k = 0; k < 128; k++) {
                float wv = W3[k*7 + c];
                a3  += g2[k]  * wv;
                cb3 += be2[k] * wv;
            }
            cb3 += b3[c];
        }
        sA3[c]  = a3;
        sCB3[c] = cb3;
    }
    __syncthreads();

    // ---- element mapping: lane 4g+j owns rows g+8j and g+8j+32 ----
    const int g  = t >> 2;
    const int jq = t & 3;
    const int r1 = g + 8*jq;
    const int r2 = r1 + 32;
    const int base = blockIdx.x * EPB + w * 64;
    const int b0r = base + r1, b1r = base + r2;
    const bool v0 = (b0r < Bn), v1 = (b1r < Bn);
    const int be0  = v0 ? b0r : (Bn - 1);
    const int be1v = v1 ? b1r : (Bn - 1);

    const int HwOff = H_B + w * 17408;
    const uint32_t Hw = smem_u32 + (uint32_t)HwOff;

    float th0[7], th1[7];
    #pragma unroll
    for (int j = 0; j < 7; j++) { th0[j] = ang[(size_t)be0*7 + j]; th1[j] = ang[(size_t)be1v*7 + j]; }
    const float vm0 = (vmk[be0]  != 0) ? 1.f : 0.f;
    const float vm1 = (vmk[be1v] != 0) ? 1.f : 0.f;
    float ssv[3];
    #pragma unroll
    for (int j = 0; j < 3; j++) ssv[j] = 1.f / (1.f + expf(-slog[j]));

    const float LOv[7] = {-2.8973f,-1.7628f,-2.8973f,-3.0718f,-2.8973f,-0.0175f,-2.8973f};
    const float HIv[7] = { 2.8973f, 1.7628f, 2.8973f,-0.0698f, 2.8973f, 3.7525f, 2.8973f};

    float kp0[21], kp1[21];
    fk_eval(th0, kp0);
    fk_eval(th1, kp1);

    float* outA = out + (size_t)28 * Bn;
    float* outK = out + (size_t)56 * Bn;

    if (v0) {
        #pragma unroll
        for (int j = 0; j < 7; j++)  outA[(size_t)be0*7 + j]  = th0[j];
        #pragma unroll
        for (int j = 0; j < 21; j++) outK[(size_t)be0*21 + j] = kp0[j];
    }
    if (v1) {
        #pragma unroll
        for (int j = 0; j < 7; j++)  outA[(size_t)be1v*7 + j]  = th1[j];
        #pragma unroll
        for (int j = 0; j < 21; j++) outK[(size_t)be1v*21 + j] = kp1[j];
    }

    // ldmatrix lane address components
    const uint32_t rowo = (uint32_t)((t < 16) ? t : (t - 16));
    const uint32_t colo = (t < 16) ? 0u : 16u;
    const uint32_t bro  = (uint32_t)(t & 7);
    const uint32_t bco  = (uint32_t)((t >> 3) & 1) * 16u;

    for (int it = 0; it < 3; it++) {
        // ---- features ----
        float x0[28], x1[28];
        float mx0 = 0.f, mx1 = 0.f;
        #pragma unroll 1
        for (int e = 0; e < 2; e++) {
            const int bb = e ? be1v : be0;
            const float vm = e ? vm1 : vm0;
            const float* kp = e ? kp1 : kp0;
            const float* th = e ? th1 : th0;
            float* x = e ? x1 : x0;
            float Rm[9], Km[6], tv[3];
            #pragma unroll
            for (int j = 0; j < 9; j++) Rm[j] = Re[(size_t)bb*9 + j];
            #pragma unroll
            for (int j = 0; j < 6; j++) Km[j] = Kc[(size_t)bb*9 + j];
            #pragma unroll
            for (int j = 0; j < 3; j++) tv[j] = te[(size_t)bb*3 + j];
            float mx = 0.f;
            #pragma unroll
            for (int k = 0; k < 7; k++) {
                float px = kp[3*k], py = kp[3*k+1], pz = kp[3*k+2];
                float cx = Rm[0]*px + Rm[1]*py + Rm[2]*pz + tv[0];
                float cy = Rm[3]*px + Rm[4]*py + Rm[5]*pz + tv[1];
                float cz = Rm[6]*px + Rm[7]*py + Rm[8]*pz + tv[2];
                float z  = fmaxf(cz, 1e-6f);
                float inv = 1.0f / z;
                float nx = cx*inv, ny = cy*inv, nz = cz*inv;
                float u = Km[0]*nx + Km[1]*ny + Km[2]*nz;
                float v = Km[3]*nx + Km[4]*ny + Km[5]*nz;
                float dx = (tgt[(size_t)bb*14 + 2*k]   - u) * vm;
                float dy = (tgt[(size_t)bb*14 + 2*k+1] - v) * vm;
                x[2*k] = dx; x[2*k+1] = dy;
                float dm = sqrtf(dx*dx + dy*dy);
                x[21+k] = dm;
                mx = fmaxf(mx, dm);
            }
            #pragma unroll
            for (int j = 0; j < 7; j++) { x[14+j] = th[j]; mx = fmaxf(mx, fabsf(th[j])); }
            if (e) mx1 = mx; else mx0 = mx;
        }
        const float s0 = 64.f / (1.f + mx0);
        const float s1 = 64.f / (1.f + mx1);

        // ---- layer 1 (scalar FFMA2): stage scaled fp16 into H rows r1/r2 ----
        float sum1a = 0.f, sq1a = 0.f, sum1b = 0.f, sq1b = 0.f;
        #pragma unroll 1
        for (int p = 0; p < 4; p++) {
            u64 acc0[16], acc1[16];
            const u64* pb1 = (const u64*)sb1 + p*16;
            #pragma unroll
            for (int i = 0; i < 16; i++) { u64 bi = pb1[i]; acc0[i] = bi; acc1[i] = bi; }
            const float* wbase = sW1 + p*32;
            #pragma unroll 4
            for (int k = 0; k < 28; k++) {
                u64 xa = pk2(x0[k], x0[k]);
                u64 xb = pk2(x1[k], x1[k]);
                const ulonglong2* wrow = (const ulonglong2*)(wbase + k*128);
                ulonglong2 wr[8];
                #pragma unroll
                for (int i = 0; i < 8; i++) wr[i] = wrow[i];
                #pragma unroll
                for (int i = 0; i < 8; i++) {
                    acc0[2*i]   = ffma2(xa, wr[i].x, acc0[2*i]);
                    acc0[2*i+1] = ffma2(xa, wr[i].y, acc0[2*i+1]);
                    acc1[2*i]   = ffma2(xb, wr[i].x, acc1[2*i]);
                    acc1[2*i+1] = ffma2(xb, wr[i].y, acc1[2*i+1]);
                }
            }
            #pragma unroll
            for (int i = 0; i < 16; i++) {
                float a0, a1; upk2(acc0[i], a0, a1);
                __half2 h2a = __float22half2_rn(make_float2(gelu_f(a0)*s0, gelu_f(a1)*s0));
                float2 ra = __half22float2(h2a);
                sum1a += ra.x + ra.y; sq1a += ra.x*ra.x + ra.y*ra.y;
                float c0v, c1v; upk2(acc1[i], c0v, c1v);
                __half2 h2b = __float22half2_rn(make_float2(gelu_f(c0v)*s1, gelu_f(c1v)*s1));
                float2 rb = __half22float2(h2b);
                sum1b += rb.x + rb.y; sq1b += rb.x*rb.x + rb.y*rb.y;
                int ho = (p*32 + 2*i) * 2;
                *(unsigned*)(smc + HwOff + r1*272 + ho) = h2_as_u32(h2a);
                *(unsigned*)(smc + HwOff + r2*272 + ho) = h2_as_u32(h2b);
            }
        }
        float mu1a = sum1a * (1.f/128.f);
        float mu1b = sum1b * (1.f/128.f);
        float rstd1a = rsqrtf(sq1a*(1.f/128.f) - mu1a*mu1a + 1e-5f*s0*s0);
        float m1av   = -mu1a * rstd1a;
        float rstd1b = rsqrtf(sq1b*(1.f/128.f) - mu1b*mu1b + 1e-5f*s1*s1);
        float m1bv   = -mu1b * rstd1b;

        // distribute per-group-row LN1 constants (8 rows per quad-group)
        float r1arr[8], m1arr[8];
        #pragma unroll
        for (int s = 0; s < 8; s++) {
            int src = (t & ~3) | (s & 3);
            float rv = (s < 4) ? rstd1a : rstd1b;
            float mv = (s < 4) ? m1av  : m1bv;
            r1arr[s] = __shfl_sync(0xffffffffu, rv, src);
            m1arr[s] = __shfl_sync(0xffffffffu, mv, src);
        }

        // ---- layer 2 via warp HMMA ----
        __syncwarp();
        float sumS[8], sqS[8], S[8][7];
        #pragma unroll
        for (int s = 0; s < 8; s++) {
            sumS[s] = 0.f; sqS[s] = 0.f;
            #pragma unroll
            for (int c = 0; c < 7; c++) S[s][c] = 0.f;
        }

        #pragma unroll 1
        for (int P = 0; P < 4; P++) {
            float C[4][4][4];
            #pragma unroll
            for (int mt = 0; mt < 4; mt++)
                #pragma unroll
                for (int nt = 0; nt < 4; nt++) {
                    C[mt][nt][0]=0.f; C[mt][nt][1]=0.f; C[mt][nt][2]=0.f; C[mt][nt][3]=0.f;
                }
            #pragma unroll 2
            for (int kt = 0; kt < 8; kt++) {
                uint32_t A0[4], A1[4], A2r[4], A3r[4];
                #pragma unroll
                for (int mt = 0; mt < 4; mt++) {
                    uint32_t ad = Hw + (16u*(uint32_t)mt + rowo)*272u + (uint32_t)kt*32u + colo;
                    LDSM4(A0[mt], A1[mt], A2r[mt], A3r[mt], ad);
                }
                uint32_t BH0[4], BH1[4], BL0[4], BL1[4];
                #pragma unroll
                for (int nt = 0; nt < 4; nt++) {
                    uint32_t nb = (uint32_t)(P*32 + nt*8);
                    uint32_t bd = smem_u32 + (nb + bro)*272u + (uint32_t)kt*32u + bco;
                    LDSM2(BH0[nt], BH1[nt], bd);
                    LDSM2(BL0[nt], BL1[nt], bd + (uint32_t)B_LO_B);
                }
                #pragma unroll
                for (int mt = 0; mt < 4; mt++)
                    #pragma unroll
                    for (int nt = 0; nt < 4; nt++) {
                        MMA16816(C[mt][nt][0],C[mt][nt][1],C[mt][nt][2],C[mt][nt][3],
                                 A0[mt],A1[mt],A2r[mt],A3r[mt], BH0[nt],BH1[nt]);
                        MMA16816(C[mt][nt][0],C[mt][nt][1],C[mt][nt][2],C[mt][nt][3],
                                 A0[mt],A1[mt],A2r[mt],A3r[mt], BL0[nt],BL1[nt]);
                    }
            }
            // pass epilogue: folded LN1 -> pre2, gelu, stats, fused GEMM3
            #pragma unroll
            for (int mt = 0; mt < 4; mt++) {
                const int sA = 2*mt, sB = 2*mt + 1;
                const float ra0 = r1arr[sA], ma0 = m1arr[sA];
                const float ra1 = r1arr[sB], ma1 = m1arr[sB];
                #pragma unroll
                for (int nt = 0; nt < 4; nt++) {
                    int u0 = P*32 + nt*8 + 2*jq;
                    float2 a2v = *(const float2*)(sA2 + u0);
                    float2 cbv = *(const float2*)(sCB2 + u0);
                    const float4* q0 = (const float4*)(sGW3 + u0*8);
                    const float4* q1 = (const float4*)(sGW3 + (u0+1)*8);
                    float4 ga = q0[0], gb = q0[1], gc = q1[0], gd = q1[1];

                    float h0 = gelu_f(fmaf(ra0, C[mt][nt][0], fmaf(ma0, a2v.x, cbv.x)));
                    float h1 = gelu_f(fmaf(ra0, C[mt][nt][1], fmaf(ma0, a2v.y, cbv.y)));
                    sumS[sA] += h0 + h1; sqS[sA] += h0*h0 + h1*h1;
                    S[sA][0] = fmaf(h0, ga.x, fmaf(h1, gc.x, S[sA][0]));
                    S[sA][1] = fmaf(h0, ga.y, fmaf(h1, gc.y, S[sA][1]));
                    S[sA][2] = fmaf(h0, ga.z, fmaf(h1, gc.z, S[sA][2]));
                    S[sA][3] = fmaf(h0, ga.w, fmaf(h1, gc.w, S[sA][3]));
                    S[sA][4] = fmaf(h0, gb.x, fmaf(h1, gd.x, S[sA][4]));
                    S[sA][5] = fmaf(h0, gb.y, fmaf(h1, gd.y, S[sA][5]));
                    S[sA][6] = fmaf(h0, gb.z, fmaf(h1, gd.z, S[sA][6]));

                    float k0 = gelu_f(fmaf(ra1, C[mt][nt][2], fmaf(ma1, a2v.x, cbv.x)));
                    float k1 = gelu_f(fmaf(ra1, C[mt][nt][3], fmaf(ma1, a2v.y, cbv.y)));
                    sumS[sB] += k0 + k1; sqS[sB] += k0*k0 + k1*k1;
                    S[sB][0] = fmaf(k0, ga.x, fmaf(k1, gc.x, S[sB][0]));
                    S[sB][1] = fmaf(k0, ga.y, fmaf(k1, gc.y, S[sB][1]));
                    S[sB][2] = fmaf(k0, ga.z, fmaf(k1, gc.z, S[sB][2]));
                    S[sB][3] = fmaf(k0, ga.w, fmaf(k1, gc.w, S[sB][3]));
                    S[sB][4] = fmaf(k0, gb.x, fmaf(k1, gd.x, S[sB][4]));
                    S[sB][5] = fmaf(k0, gb.y, fmaf(k1, gd.y, S[sB][5]));
                    S[sB][6] = fmaf(k0, gb.z, fmaf(k1, gd.z, S[sB][6]));
                }
            }
        }
        __syncwarp();

        // quad reductions
        #pragma unroll
        for (int s = 0; s < 8; s++) {
            sumS[s] += __shfl_xor_sync(0xffffffffu, sumS[s], 1);
            sumS[s] += __shfl_xor_sync(0xffffffffu, sumS[s], 2);
            sqS[s]  += __shfl_xor_sync(0xffffffffu, sqS[s], 1);
            sqS[s]  += __shfl_xor_sync(0xffffffffu, sqS[s], 2);
            #pragma unroll
            for (int c = 0; c < 7; c++) {
                S[s][c] += __shfl_xor_sync(0xffffffffu, S[s][c], 1);
                S[s][c] += __shfl_xor_sync(0xffffffffu, S[s][c], 2);
            }
        }
        // extract own rows (s = jq for elem0, s = jq+4 for elem1) via predicated selects
        float suA = 0.f, sqA = 0.f, suB = 0.f, sqB = 0.f;
        float SA[7] = {0,0,0,0,0,0,0}, SB[7] = {0,0,0,0,0,0,0};
        #pragma unroll
        for (int s = 0; s < 4; s++) {
            if (jq == s) {
                suA = sumS[s];   sqA = sqS[s];
                suB = sumS[s+4]; sqB = sqS[s+4];
                #pragma unroll
                for (int c = 0; c < 7; c++) { SA[c] = S[s][c]; SB[c] = S[s+4][c]; }
            }
        }

        float mu2a   = suA * (1.f/128.f);
        float rstd2a = rsqrtf(sqA * (1.f/128.f) - mu2a*mu2a + 1e-5f);
        float m2a    = -mu2a * rstd2a;
        float mu2b   = suB * (1.f/128.f);
        float rstd2b = rsqrtf(sqB * (1.f/128.f) - mu2b*mu2b + 1e-5f);
        float m2b    = -mu2b * rstd2b;

        float ss = ssv[it];
        #pragma unroll
        for (int j = 0; j < 7; j++) {
            float d0 = fmaf(rstd2a, SA[j], fmaf(m2a, sA3[j], sCB3[j]));
            float n0 = th0[j] + ss * d0;
            th0[j] = fminf(fmaxf(n0, LOv[j]), HIv[j]);
            float d1 = fmaf(rstd2b, SB[j], fmaf(m2b, sA3[j], sCB3[j]));
            float n1 = th1[j] + ss * d1;
            th1[j] = fminf(fmaxf(n1, LOv[j]), HIv[j]);
        }
        fk_eval(th0, kp0);
        fk_eval(th1, kp1);

        const size_t wv = (size_t)(it + 1);
        if (v0) {
            #pragma unroll
            for (int j = 0; j < 7; j++)  outA[wv*(size_t)Bn*7  + (size_t)be0*7  + j] = th0[j];
            #pragma unroll
            for (int j = 0; j < 21; j++) outK[wv*(size_t)Bn*21 + (size_t)be0*21 + j] = kp0[j];
        }
        if (v1) {
            #pragma unroll
            for (int j = 0; j < 7; j++)  outA[wv*(size_t)Bn*7  + (size_t)be1v*7  + j] = th1[j];
            #pragma unroll
            for (int j = 0; j < 21; j++) outK[wv*(size_t)Bn*21 + (size_t)be1v*21 + j] = kp1[j];
        }
    }

    if (v0) {
        #pragma unroll
        for (int j = 0; j < 7; j++)  out[(size_t)be0*7 + j] = th0[j];
        #pragma unroll
        for (int j = 0; j < 21; j++) out[(size_t)7*Bn + (size_t)be0*21 + j] = kp0[j];
    }
    if (v1) {
        #pragma unroll
        for (int j = 0; j < 7; j++)  out[(size_t)be1v*7 + j] = th1[j];
        #pragma unroll
        for (int j = 0; j < 21; j++) out[(size_t)7*Bn + (size_t)be1v*21 + j] = kp1[j];
    }
}

extern "C" void kernel_launch(void* const* d_in, const int* in_sizes, int n_in,
                              void* d_out, int out_size)
{
    const float* ang  = (const float*)d_in[0];
    const float* tgt  = (const float*)d_in[1];
    const float* Kc   = (const float*)d_in[2];
    const float* Re   = (const float*)d_in[4];
    const float* te   = (const float*)d_in[5];
    const int*   vmk  = (const int*)d_in[6];
    const float* W1   = (const float*)d_in[7];
    const float* b1   = (const float*)d_in[8];
    const float* g1   = (const float*)d_in[9];
    const float* be1  = (const float*)d_in[10];
    const float* W2   = (const float*)d_in[11];
    const float* b2   = (const float*)d_in[12];
    const float* g2   = (const float*)d_in[13];
    const float* be2  = (const float*)d_in[14];
    const float* W3   = (const float*)d_in[15];
    const float* b3   = (const float*)d_in[16];
    const float* slog = (const float*)d_in[17];

    const int Bn = in_sizes[0] / 7;
    const size_t smem = (size_t)SMEM_FLOATS * sizeof(float);

    cudaFuncSetAttribute(irm_kernel, cudaFuncAttributeMaxDynamicSharedMemorySize, (int)smem);

    const int grid = (Bn + EPB - 1) / EPB;
    irm_kernel<<<grid, TPB, smem>>>(ang, tgt, Kc, Re, te, vmk,
                                    W1, b1, g1, be1, W2, b2, g2, be2, W3, b3,
                                    slog, (float*)d_out, Bn);
}